// round 12
// baseline (speedup 1.0000x reference)
#include <cuda_runtime.h>
#include <cuda_bf16.h>
#include <math.h>
#include <stdint.h>

#define NB   8
#define CIN  64
#define CO   128
#define HH0  256
#define WW0  256
#define HWSZ 65536
#define HD   128
#define WD   128

// ---------------- scratch ----------------
__device__ float g_wsn[CO*CIN*9];
__device__ unsigned char g_wB[9*34816];     // per-tap [hi|lo][64 c-rows x 272B (128 o bf16 + pad)]
__device__ float g_ratio[NB*HWSZ];
__device__ float g_mvalid[NB*HWSZ];
__device__ float g_y[(size_t)NB*CO*HWSZ];
__device__ float g_mlo[NB*HD*WW0];
__device__ float g_mhi[NB*HD*WW0];

__constant__ float c_H0[9] = {
    0.026748757410810f, -0.016864118442875f, -0.078223266528990f,
    0.266864118442875f,  0.602949018236360f,  0.266864118442875f,
   -0.078223266528990f, -0.016864118442875f,  0.026748757410810f};
__constant__ float c_H1[7] = {
    0.091271763114250f, -0.057543526228500f, -0.591271763114250f,
    1.115087052457000f, -0.591271763114250f, -0.057543526228500f,
    0.091271763114250f};

#define SZ_BAND ((size_t)NB*CO*HD*WD)
#define SZ_MASK ((size_t)NB*HD*WD)
#define OFS_LL   ((size_t)0)
#define OFS_MLL  (OFS_LL  + SZ_BAND)
#define OFS_LH   (OFS_MLL + SZ_MASK)
#define OFS_HL   (OFS_LH  + SZ_BAND)
#define OFS_HH   (OFS_HL  + SZ_BAND)
#define OFS_MLH  (OFS_HH  + SZ_BAND)
#define OFS_MHL  (OFS_MLH + SZ_MASK)
#define OFS_MHH  (OFS_MHL + SZ_MASK)

__device__ __forceinline__ int refl(int j, int n) {
    if (j < 0) j = -j;
    if (j >= n) j = 2*n - 2 - j;
    return j;
}

// ---------------- mma.sync / ldmatrix / cp.async helpers (baseline PTX, sm_80+) ----------
__device__ __forceinline__ uint32_t smem_u32(const void* p) {
    uint32_t a;
    asm("{ .reg .u64 t; cvta.to.shared.u64 t, %1; cvt.u32.u64 %0, t; }" : "=r"(a) : "l"(p));
    return a;
}
__device__ __forceinline__ void ldsm4(uint32_t* r, uint32_t a) {
    asm volatile("ldmatrix.sync.aligned.m8n8.x4.shared.b16 {%0,%1,%2,%3}, [%4];"
        : "=r"(r[0]), "=r"(r[1]), "=r"(r[2]), "=r"(r[3]) : "r"(a));
}
__device__ __forceinline__ void ldsm4t(uint32_t* r, uint32_t a) {
    asm volatile("ldmatrix.sync.aligned.m8n8.x4.trans.shared.b16 {%0,%1,%2,%3}, [%4];"
        : "=r"(r[0]), "=r"(r[1]), "=r"(r[2]), "=r"(r[3]) : "r"(a));
}
__device__ __forceinline__ void mma16816(float* c, const uint32_t* a, const uint32_t* b) {
    asm volatile("mma.sync.aligned.m16n8k16.row.col.f32.bf16.bf16.f32 "
        "{%0,%1,%2,%3},{%4,%5,%6,%7},{%8,%9},{%0,%1,%2,%3};"
        : "+f"(c[0]), "+f"(c[1]), "+f"(c[2]), "+f"(c[3])
        : "r"(a[0]), "r"(a[1]), "r"(a[2]), "r"(a[3]), "r"(b[0]), "r"(b[1]));
}
__device__ __forceinline__ void cpa16(uint32_t s, const void* g) {
    asm volatile("cp.async.cg.shared.global [%0], [%1], 16;" :: "r"(s), "l"(g) : "memory");
}
__device__ __forceinline__ void cpa_commit() {
    asm volatile("cp.async.commit_group;" ::: "memory");
}
__device__ __forceinline__ void cpa_wait0() {
    asm volatile("cp.async.wait_group 0;" ::: "memory");
}

// ---------------- K0: spectral norm -> g_wsn ----------------
__global__ void k_sigma(const float* __restrict__ w, const float* __restrict__ u) {
    __shared__ float sv[576];
    __shared__ float red[576];
    __shared__ float s_bcast;
    int t = threadIdx.x;

    float vj = 0.f;
    for (int o = 0; o < CO; ++o) vj += w[o*576 + t] * u[o];
    red[t] = vj*vj;
    sv[t] = vj;
    __syncthreads();
    if (t == 0) {
        float s = 0.f;
        for (int i = 0; i < 576; ++i) s += red[i];
        s_bcast = 1.f / (sqrtf(s) + 1e-12f);
    }
    __syncthreads();
    float vn = sv[t] * s_bcast;
    __syncthreads();
    sv[t] = vn;
    __syncthreads();

    if (t < CO) {
        float s = 0.f;
        for (int j = 0; j < 576; ++j) s += w[t*576 + j] * sv[j];
        red[t] = s*s;
    }
    __syncthreads();
    if (t == 0) {
        float s = 0.f;
        for (int i = 0; i < CO; ++i) s += red[i];
        s_bcast = 1.f / sqrtf(s);
    }
    __syncthreads();
    float inv_sigma = s_bcast;
    for (int i = t; i < CO*CIN*9; i += 576) g_wsn[i] = w[i] * inv_sigma;
}

// ---------------- K0b: weights -> per-tap [c][o] bf16 hi/lo rows (272B stride) --------
__global__ void k_prepw() {
    int idx = blockIdx.x*256 + threadIdx.x;
    if (idx >= 9*CIN*CO) return;
    int q = idx >> 13;
    int rem = idx & 8191;
    int c = rem >> 7;
    int o = rem & 127;
    float v = g_wsn[(o*CIN + c)*9 + q];
    __nv_bfloat16 hi = __float2bfloat16(v);
    __nv_bfloat16 lo = __float2bfloat16(v - __bfloat162float(hi));
    size_t base = (size_t)q*34816;
    *(__nv_bfloat16*)(g_wB + base +         c*272 + o*2) = hi;
    *(__nv_bfloat16*)(g_wB + base + 17408 + c*272 + o*2) = lo;
}

// ---------------- K1: mask 3x3 box -> ratio + valid ----------------
__global__ void k_ratio(const float* __restrict__ mask) {
    int idx = blockIdx.x*256 + threadIdx.x;
    int b = idx >> 16;
    int hw = idx & 65535;
    int h = hw >> 8, wx = hw & 255;
    const float* mb = mask + (size_t)b*HWSZ;
    float s = 0.f;
    #pragma unroll
    for (int dh = -1; dh <= 1; ++dh) {
        int h2 = h + dh;
        if (h2 < 0 || h2 >= HH0) continue;
        #pragma unroll
        for (int dw = -1; dw <= 1; ++dw) {
            int w2 = wx + dw;
            if (w2 < 0 || w2 >= WW0) continue;
            s += mb[h2*WW0 + w2];
        }
    }
    bool valid = s > 0.f;
    g_mvalid[idx] = valid ? 1.f : 0.f;
    g_ratio[idx]  = valid ? 9.f / fmaxf(s, 1e-8f) : 0.f;
}

// ---------------- K2: mma.sync implicit-GEMM conv (bf16 3-term split) ----------------
// Single-buffered weights -> smem 110848 -> 2 CTAs/SM.
#define P_HI 0
#define P_LO 38016
#define BW0  76032
#define SMEM_MMA 110848

extern __shared__ char smc[];

__global__ void __launch_bounds__(256, 2) k_conv_mma(const float* __restrict__ x,
                                                     const float* __restrict__ mask,
                                                     const float* __restrict__ bias) {
    uint32_t sb = smem_u32(smc);
    int t = threadIdx.x, l = t & 31, wid = t >> 5;
    int w0 = blockIdx.x * 64, h0 = blockIdx.y * 2, b = blockIdx.z;
    int warp_m = wid & 1;
    int warp_n = wid >> 1;

    // prefetch tap 0
    for (int i = t; i < 2176; i += 256)
        cpa16(sb + BW0 + i*16, g_wB + i*16);
    cpa_commit();

    // patch fill: 64c x 4rows x 66w of (x*mask), bf16 hi/lo
    for (int i = t; i < 16896; i += 256) {
        int w = i % 66;
        int rem = i / 66;
        int r = rem & 3;
        int c = rem >> 2;
        int h = h0 - 1 + r, wx = w0 - 1 + w;
        float v = 0.f;
        if (h >= 0 && h < HH0 && wx >= 0 && wx < WW0)
            v = x[(((size_t)b*CIN + c)*HH0 + h)*WW0 + wx]
              * mask[((size_t)b*HH0 + h)*WW0 + wx];
        __nv_bfloat16 hi = __float2bfloat16(v);
        __nv_bfloat16 lo = __float2bfloat16(v - __bfloat162float(hi));
        int off = (r*66 + w)*144 + c*2;
        *(__nv_bfloat16*)(smc + P_HI + off) = hi;
        *(__nv_bfloat16*)(smc + P_LO + off) = lo;
    }
    cpa_wait0();
    __syncthreads();

    float acc[4][4][4];
    #pragma unroll
    for (int mi = 0; mi < 4; ++mi)
        #pragma unroll
        for (int ni = 0; ni < 4; ++ni)
            #pragma unroll
            for (int k = 0; k < 4; ++k) acc[mi][ni][k] = 0.f;

    int lane15 = l & 15;
    int kh8 = ((l >> 4) & 1) * 8;
    int noff = ((l >> 4) & 1) * 8;

    for (int q = 0; q < 9; ++q) {
        int kh = q / 3, kw = q - kh*3;
        uint32_t bwbase = sb + BW0;
        int prow0 = ((warp_m + kh)*66 + kw) * 144;

        #pragma unroll
        for (int ks = 0; ks < 4; ++ks) {
            int k0 = ks * 16;
            uint32_t aH[4][4], aL[4][4];
            #pragma unroll
            for (int mi = 0; mi < 4; ++mi) {
                uint32_t off = (uint32_t)(prow0 + (mi*16 + lane15)*144 + (k0 + kh8)*2);
                ldsm4(aH[mi], sb + P_HI + off);
                ldsm4(aL[mi], sb + P_LO + off);
            }
            uint32_t bH[2][4], bL[2][4];
            #pragma unroll
            for (int n2 = 0; n2 < 2; ++n2) {
                uint32_t boff = (uint32_t)((k0 + lane15)*272 + (warp_n*32 + n2*16 + noff)*2);
                ldsm4t(bH[n2], bwbase + boff);
                ldsm4t(bL[n2], bwbase + 17408 + boff);
            }
            #pragma unroll
            for (int mi = 0; mi < 4; ++mi)
                #pragma unroll
                for (int ni = 0; ni < 4; ++ni) {
                    const uint32_t* bh = &bH[ni >> 1][(ni & 1)*2];
                    const uint32_t* bl = &bL[ni >> 1][(ni & 1)*2];
                    mma16816(acc[mi][ni], aH[mi], bh);
                    mma16816(acc[mi][ni], aH[mi], bl);
                    mma16816(acc[mi][ni], aL[mi], bh);
                }
        }

        __syncthreads();    // all warps done reading BW0 before overwrite
        if (q < 8) {
            const unsigned char* src = g_wB + (size_t)(q + 1)*34816;
            for (int i = t; i < 2176; i += 256)
                cpa16(sb + BW0 + i*16, src + i*16);
            cpa_commit();
            cpa_wait0();
            __syncthreads();
        }
    }

    __syncthreads();
    float* D = (float*)smc;
    #pragma unroll
    for (int mi = 0; mi < 4; ++mi)
        #pragma unroll
        for (int ni = 0; ni < 4; ++ni) {
            int px = warp_m*64 + mi*16 + (l >> 2);
            int o  = warp_n*32 + ni*8 + 2*(l & 3);
            D[o*130 + px]           = acc[mi][ni][0];
            D[(o + 1)*130 + px]     = acc[mi][ni][1];
            D[o*130 + px + 8]       = acc[mi][ni][2];
            D[(o + 1)*130 + px + 8] = acc[mi][ni][3];
        }
    __syncthreads();

    int wp = t & 63, og = t >> 6;
    #pragma unroll
    for (int r = 0; r < 2; ++r) {
        int h = h0 + r;
        int wg = w0 + wp;
        float rt = g_ratio[((size_t)b*HH0 + h)*WW0 + wg];
        #pragma unroll 8
        for (int oo = 0; oo < 32; ++oo) {
            int o = oo*4 + og;
            float v = D[o*130 + r*64 + wp];
            g_y[(((size_t)b*CO + o)*HH0 + h)*WW0 + wg] = (rt > 0.f) ? v*rt + bias[o] : 0.f;
        }
    }
}

// ---------------- K3: GDN (in-place), smem-cached y tile, single gmem read+write ------
// ys[128c][128px] cached once; z squared on the fly; epilogue reads ys.
#define GDN_GS 65536            // gsT[16][132] after ys (65536B)
#define SMEM_GDN 73984

__global__ void __launch_bounds__(256) k_gdn(const float* __restrict__ gamma,
                                             const float* __restrict__ beta) {
    float* ys  = (float*)smc;                  // [c][128]
    float* gsT = (float*)(smc + GDN_GS);       // [k][132]

    size_t p0 = (size_t)blockIdx.x * 128;
    int b   = (int)(p0 >> 16);
    int hw0 = (int)(p0 & 65535);
    int t = threadIdx.x;
    int px = t & 15, oy = t >> 4;

    float* yb = g_y + (size_t)b*CO*HWSZ + hw0;

    // cache the full y tile (coalesced float4)
    for (int i = t; i < 4096; i += 256) {
        int c = i >> 5, w4 = (i & 31) * 4;
        *(float4*)&ys[c*128 + w4] = *(const float4*)&yb[(size_t)c*HWSZ + w4];
    }
    __syncthreads();

    float acc[8][8];
    #pragma unroll
    for (int i = 0; i < 8; ++i)
        #pragma unroll
        for (int j = 0; j < 8; ++j) acc[i][j] = 0.f;

    for (int c0 = 0; c0 < CO; c0 += 16) {
        for (int i = t; i < 2048; i += 256) {        // gamma chunk transposed [k][o]
            int o = i >> 4, k = i & 15;
            gsT[k*132 + o] = gamma[o*CO + c0 + k];
        }
        __syncthreads();
        #pragma unroll
        for (int k = 0; k < 16; ++k) {
            float4 a0 = *(const float4*)&gsT[k*132 + oy*8];
            float4 a1 = *(const float4*)&gsT[k*132 + oy*8 + 4];
            float4 b0 = *(const float4*)&ys[(c0 + k)*128 + px*8];
            float4 b1 = *(const float4*)&ys[(c0 + k)*128 + px*8 + 4];
            float a[8] = {a0.x, a0.y, a0.z, a0.w, a1.x, a1.y, a1.z, a1.w};
            float bb[8] = {b0.x*b0.x, b0.y*b0.y, b0.z*b0.z, b0.w*b0.w,
                           b1.x*b1.x, b1.y*b1.y, b1.z*b1.z, b1.w*b1.w};
            #pragma unroll
            for (int i = 0; i < 8; ++i)
                #pragma unroll
                for (int j = 0; j < 8; ++j) acc[i][j] += a[i]*bb[j];
        }
        __syncthreads();    // before next gsT overwrite
    }

    float4 m0 = *(const float4*)&g_mvalid[p0 + px*8];
    float4 m1 = *(const float4*)&g_mvalid[p0 + px*8 + 4];
    float mv[8] = {m0.x, m0.y, m0.z, m0.w, m1.x, m1.y, m1.z, m1.w};
    #pragma unroll
    for (int i = 0; i < 8; ++i) {
        int o = oy*8 + i;
        float bo = beta[o];
        const float* yr = &ys[o*128 + px*8];
        float4 r0, r1;
        r0.x = yr[0] * rsqrtf(bo + acc[i][0]) * mv[0];
        r0.y = yr[1] * rsqrtf(bo + acc[i][1]) * mv[1];
        r0.z = yr[2] * rsqrtf(bo + acc[i][2]) * mv[2];
        r0.w = yr[3] * rsqrtf(bo + acc[i][3]) * mv[3];
        r1.x = yr[4] * rsqrtf(bo + acc[i][4]) * mv[4];
        r1.y = yr[5] * rsqrtf(bo + acc[i][5]) * mv[5];
        r1.z = yr[6] * rsqrtf(bo + acc[i][6]) * mv[6];
        r1.w = yr[7] * rsqrtf(bo + acc[i][7]) * mv[7];
        size_t ad = (size_t)o*HWSZ + px*8;
        *(float4*)&yb[ad]     = r0;
        *(float4*)&yb[ad + 4] = r1;
    }
}

// ---------------- K4: fused DWT (rows + cols in one pass) -> 4 bands ----------------
#define DX_OFS 0          // xs[39][256] floats
#define DL_OFS 9984       // lo[16][260]
#define DH_OFS 14144      // hi[16][260]
#define SMEM_DWT 73216    // 18304 floats

__global__ void __launch_bounds__(256) k_dwt_fused(float* __restrict__ out) {
    float* sm = (float*)smc;
    float* xs = sm + DX_OFS;
    float* lo = sm + DL_OFS;
    float* hi = sm + DH_OFS;

    int t = threadIdx.x;
    int hr0 = blockIdx.x * 16;
    int bc  = blockIdx.y;
    const float* img = g_y + (size_t)bc*HWSZ;

    for (int i = t; i < 9984; i += 256) {
        int r = i >> 8, w = i & 255;
        int h = refl(2*hr0 - 4 + r, HH0);
        xs[r*256 + w] = img[h*WW0 + w];
    }
    __syncthreads();

    {
        int w = t;
        #pragma unroll 4
        for (int d = 0; d < 16; ++d) {
            const float* col = xs + 2*d*256 + w;
            float a0 = col[0],      a1 = col[256],  a2 = col[512],  a3 = col[768];
            float a4 = col[1024],   a5 = col[1280], a6 = col[1536], a7 = col[1792];
            float a8 = col[2048];
            float lv = c_H0[0]*a0 + c_H0[1]*a1 + c_H0[2]*a2 + c_H0[3]*a3 + c_H0[4]*a4
                     + c_H0[5]*a5 + c_H0[6]*a6 + c_H0[7]*a7 + c_H0[8]*a8;
            float hv = c_H1[0]*a1 + c_H1[1]*a2 + c_H1[2]*a3 + c_H1[3]*a4
                     + c_H1[4]*a5 + c_H1[5]*a6 + c_H1[6]*a7;
            lo[d*260 + w] = lv;
            hi[d*260 + w] = hv;
        }
    }
    __syncthreads();

    size_t obase = (size_t)bc*HD*WD;
    for (int i = t; i < 2048; i += 256) {
        int wr = i & 127, d = i >> 7;
        const float* lrow = lo + d*260;
        const float* hrow = hi + d*260;
        float rl[9], rh[9];
        #pragma unroll
        for (int k = 0; k < 9; ++k) {
            int j = refl(2*wr + k - 4, WW0);
            rl[k] = lrow[j];
            rh[k] = hrow[j];
        }
        float ll = 0.f, lh = 0.f, hl = 0.f, hh = 0.f;
        #pragma unroll
        for (int k = 0; k < 9; ++k) { ll += c_H0[k]*rl[k]; hl += c_H0[k]*rh[k]; }
        #pragma unroll
        for (int k = 0; k < 7; ++k) { lh += c_H1[k]*rl[k+1]; hh += c_H1[k]*rh[k+1]; }
        size_t oidx = obase + (size_t)(hr0 + d)*WD + wr;
        out[OFS_LL + oidx] = ll;
        out[OFS_LH + oidx] = lh;
        out[OFS_HL + oidx] = hl;
        out[OFS_HH + oidx] = hh;
    }
}

// ---------------- K6: mask downsample along H ----------------
__global__ void k_mask_rows() {
    int idx = blockIdx.x*256 + threadIdx.x;
    int wx = idx & 255;
    int hr = (idx >> 8) & 127;
    int b  = idx >> 15;
    const float* mb = g_mvalid + (size_t)b*HWSZ + wx;
    float s9 = 0.f, s7 = 0.f;
    #pragma unroll
    for (int k = 0; k < 9; ++k) {
        float v = mb[refl(2*hr + k - 4, HH0) * WW0];
        s9 += v;
        if (k >= 1 && k <= 7) s7 += v;
    }
    g_mlo[idx] = (s9 > 0.f) ? 1.f : 0.f;
    g_mhi[idx] = (s7 > 0.f) ? 1.f : 0.f;
}

// ---------------- K7: mask downsample along W -> out ----------------
__global__ void k_mask_cols(float* __restrict__ out) {
    int idx = blockIdx.x*256 + threadIdx.x;
    int wr = idx & 127;
    int hr = (idx >> 7) & 127;
    int b  = idx >> 14;
    const float* lrow = g_mlo + ((size_t)b*HD + hr)*WW0;
    const float* hrow = g_mhi + ((size_t)b*HD + hr)*WW0;
    float s9l = 0.f, s7l = 0.f, s9h = 0.f, s7h = 0.f;
    #pragma unroll
    for (int k = 0; k < 9; ++k) {
        int j = refl(2*wr + k - 4, WW0);
        float vl = lrow[j], vh = hrow[j];
        s9l += vl; s9h += vh;
        if (k >= 1 && k <= 7) { s7l += vl; s7h += vh; }
    }
    out[OFS_MLL + idx] = (s9l > 0.f) ? 1.f : 0.f;
    out[OFS_MLH + idx] = (s7l > 0.f) ? 1.f : 0.f;
    out[OFS_MHL + idx] = (s9h > 0.f) ? 1.f : 0.f;
    out[OFS_MHH + idx] = (s7h > 0.f) ? 1.f : 0.f;
}

// ---------------- launch ----------------
extern "C" void kernel_launch(void* const* d_in, const int* in_sizes, int n_in,
                              void* d_out, int out_size) {
    const float* tensor = (const float*)d_in[0];
    const float* mask   = (const float*)d_in[1];
    const float* weight = (const float*)d_in[2];
    const float* bias   = (const float*)d_in[3];
    const float* u      = (const float*)d_in[4];
    const float* beta   = (const float*)d_in[5];
    const float* gamma  = (const float*)d_in[6];
    float* out = (float*)d_out;

    cudaFuncSetAttribute(k_conv_mma, cudaFuncAttributeMaxDynamicSharedMemorySize, SMEM_MMA);
    cudaFuncSetAttribute(k_gdn, cudaFuncAttributeMaxDynamicSharedMemorySize, SMEM_GDN);
    cudaFuncSetAttribute(k_dwt_fused, cudaFuncAttributeMaxDynamicSharedMemorySize, SMEM_DWT);

    k_sigma<<<1, 576>>>(weight, u);
    k_prepw<<<288, 256>>>();
    k_ratio<<<(NB*HWSZ)/256, 256>>>(mask);
    k_conv_mma<<<dim3(4, 128, NB), 256, SMEM_MMA>>>(tensor, mask, bias);
    k_gdn<<<(NB*HWSZ)/128, 256, SMEM_GDN>>>(gamma, beta);
    k_dwt_fused<<<dim3(8, NB*CO), 256, SMEM_DWT>>>(out);
    k_mask_rows<<<(NB*HD*WW0)/256, 256>>>();
    k_mask_cols<<<(NB*HD*WD)/256, 256>>>(out);
}

// round 13
// speedup vs baseline: 1.5078x; 1.5078x over previous
#include <cuda_runtime.h>
#include <cuda_bf16.h>
#include <math.h>
#include <stdint.h>

#define NB   8
#define CIN  64
#define CO   128
#define HH0  256
#define WW0  256
#define HWSZ 65536
#define HD   128
#define WD   128

// ---------------- scratch ----------------
__device__ float g_wsn[CO*CIN*9];
__device__ unsigned char g_wB[9*34816];     // per-tap [hi|lo][64 c-rows x 272B (128 o bf16 + pad)]
__device__ float g_ratio[NB*HWSZ];
__device__ float g_mvalid[NB*HWSZ];
__device__ float g_y[(size_t)NB*CO*HWSZ];

__constant__ float c_H0[9] = {
    0.026748757410810f, -0.016864118442875f, -0.078223266528990f,
    0.266864118442875f,  0.602949018236360f,  0.266864118442875f,
   -0.078223266528990f, -0.016864118442875f,  0.026748757410810f};
__constant__ float c_H1[7] = {
    0.091271763114250f, -0.057543526228500f, -0.591271763114250f,
    1.115087052457000f, -0.591271763114250f, -0.057543526228500f,
    0.091271763114250f};

#define SZ_BAND ((size_t)NB*CO*HD*WD)
#define SZ_MASK ((size_t)NB*HD*WD)
#define OFS_LL   ((size_t)0)
#define OFS_MLL  (OFS_LL  + SZ_BAND)
#define OFS_LH   (OFS_MLL + SZ_MASK)
#define OFS_HL   (OFS_LH  + SZ_BAND)
#define OFS_HH   (OFS_HL  + SZ_BAND)
#define OFS_MLH  (OFS_HH  + SZ_BAND)
#define OFS_MHL  (OFS_MLH + SZ_MASK)
#define OFS_MHH  (OFS_MHL + SZ_MASK)

__device__ __forceinline__ int refl(int j, int n) {
    if (j < 0) j = -j;
    if (j >= n) j = 2*n - 2 - j;
    return j;
}

// ---------------- mma.sync / ldmatrix / cp.async helpers (baseline PTX, sm_80+) ----------
__device__ __forceinline__ uint32_t smem_u32(const void* p) {
    uint32_t a;
    asm("{ .reg .u64 t; cvta.to.shared.u64 t, %1; cvt.u32.u64 %0, t; }" : "=r"(a) : "l"(p));
    return a;
}
__device__ __forceinline__ void ldsm4(uint32_t* r, uint32_t a) {
    asm volatile("ldmatrix.sync.aligned.m8n8.x4.shared.b16 {%0,%1,%2,%3}, [%4];"
        : "=r"(r[0]), "=r"(r[1]), "=r"(r[2]), "=r"(r[3]) : "r"(a));
}
__device__ __forceinline__ void ldsm4t(uint32_t* r, uint32_t a) {
    asm volatile("ldmatrix.sync.aligned.m8n8.x4.trans.shared.b16 {%0,%1,%2,%3}, [%4];"
        : "=r"(r[0]), "=r"(r[1]), "=r"(r[2]), "=r"(r[3]) : "r"(a));
}
__device__ __forceinline__ void mma16816(float* c, const uint32_t* a, const uint32_t* b) {
    asm volatile("mma.sync.aligned.m16n8k16.row.col.f32.bf16.bf16.f32 "
        "{%0,%1,%2,%3},{%4,%5,%6,%7},{%8,%9},{%0,%1,%2,%3};"
        : "+f"(c[0]), "+f"(c[1]), "+f"(c[2]), "+f"(c[3])
        : "r"(a[0]), "r"(a[1]), "r"(a[2]), "r"(a[3]), "r"(b[0]), "r"(b[1]));
}
__device__ __forceinline__ void cpa16(uint32_t s, const void* g) {
    asm volatile("cp.async.cg.shared.global [%0], [%1], 16;" :: "r"(s), "l"(g) : "memory");
}
__device__ __forceinline__ void cpa_commit() {
    asm volatile("cp.async.commit_group;" ::: "memory");
}
__device__ __forceinline__ void cpa_wait0() {
    asm volatile("cp.async.wait_group 0;" ::: "memory");
}

// ---------------- K0: spectral norm -> g_wsn ----------------
__global__ void k_sigma(const float* __restrict__ w, const float* __restrict__ u) {
    __shared__ float sv[576];
    __shared__ float red[576];
    __shared__ float s_bcast;
    int t = threadIdx.x;

    float vj = 0.f;
    for (int o = 0; o < CO; ++o) vj += w[o*576 + t] * u[o];
    red[t] = vj*vj;
    sv[t] = vj;
    __syncthreads();
    if (t == 0) {
        float s = 0.f;
        for (int i = 0; i < 576; ++i) s += red[i];
        s_bcast = 1.f / (sqrtf(s) + 1e-12f);
    }
    __syncthreads();
    float vn = sv[t] * s_bcast;
    __syncthreads();
    sv[t] = vn;
    __syncthreads();

    if (t < CO) {
        float s = 0.f;
        for (int j = 0; j < 576; ++j) s += w[t*576 + j] * sv[j];
        red[t] = s*s;
    }
    __syncthreads();
    if (t == 0) {
        float s = 0.f;
        for (int i = 0; i < CO; ++i) s += red[i];
        s_bcast = 1.f / sqrtf(s);
    }
    __syncthreads();
    float inv_sigma = s_bcast;
    for (int i = t; i < CO*CIN*9; i += 576) g_wsn[i] = w[i] * inv_sigma;
}

// ---------------- K0b: weights -> per-tap [c][o] bf16 hi/lo rows (272B stride) --------
__global__ void k_prepw() {
    int idx = blockIdx.x*256 + threadIdx.x;
    if (idx >= 9*CIN*CO) return;
    int q = idx >> 13;
    int rem = idx & 8191;
    int c = rem >> 7;
    int o = rem & 127;
    float v = g_wsn[(o*CIN + c)*9 + q];
    __nv_bfloat16 hi = __float2bfloat16(v);
    __nv_bfloat16 lo = __float2bfloat16(v - __bfloat162float(hi));
    size_t base = (size_t)q*34816;
    *(__nv_bfloat16*)(g_wB + base +         c*272 + o*2) = hi;
    *(__nv_bfloat16*)(g_wB + base + 17408 + c*272 + o*2) = lo;
}

// ---------------- K1: mask 3x3 box -> ratio + valid ----------------
__global__ void k_ratio(const float* __restrict__ mask) {
    int idx = blockIdx.x*256 + threadIdx.x;
    int b = idx >> 16;
    int hw = idx & 65535;
    int h = hw >> 8, wx = hw & 255;
    const float* mb = mask + (size_t)b*HWSZ;
    float s = 0.f;
    #pragma unroll
    for (int dh = -1; dh <= 1; ++dh) {
        int h2 = h + dh;
        if (h2 < 0 || h2 >= HH0) continue;
        #pragma unroll
        for (int dw = -1; dw <= 1; ++dw) {
            int w2 = wx + dw;
            if (w2 < 0 || w2 >= WW0) continue;
            s += mb[h2*WW0 + w2];
        }
    }
    bool valid = s > 0.f;
    g_mvalid[idx] = valid ? 1.f : 0.f;
    g_ratio[idx]  = valid ? 9.f / fmaxf(s, 1e-8f) : 0.f;
}

// ---------------- K2: mma.sync implicit-GEMM conv (bf16 3-term split) ----------------
// Single-buffered weights -> smem 110848 -> 2 CTAs/SM.
#define P_HI 0
#define P_LO 38016
#define BW0  76032
#define SMEM_MMA 110848

extern __shared__ char smc[];

__global__ void __launch_bounds__(256, 2) k_conv_mma(const float* __restrict__ x,
                                                     const float* __restrict__ mask,
                                                     const float* __restrict__ bias) {
    uint32_t sb = smem_u32(smc);
    int t = threadIdx.x, l = t & 31, wid = t >> 5;
    int w0 = blockIdx.x * 64, h0 = blockIdx.y * 2, b = blockIdx.z;
    int warp_m = wid & 1;
    int warp_n = wid >> 1;

    // prefetch tap 0
    for (int i = t; i < 2176; i += 256)
        cpa16(sb + BW0 + i*16, g_wB + i*16);
    cpa_commit();

    // patch fill: 64c x 4rows x 66w of (x*mask), bf16 hi/lo
    for (int i = t; i < 16896; i += 256) {
        int w = i % 66;
        int rem = i / 66;
        int r = rem & 3;
        int c = rem >> 2;
        int h = h0 - 1 + r, wx = w0 - 1 + w;
        float v = 0.f;
        if (h >= 0 && h < HH0 && wx >= 0 && wx < WW0)
            v = x[(((size_t)b*CIN + c)*HH0 + h)*WW0 + wx]
              * mask[((size_t)b*HH0 + h)*WW0 + wx];
        __nv_bfloat16 hi = __float2bfloat16(v);
        __nv_bfloat16 lo = __float2bfloat16(v - __bfloat162float(hi));
        int off = (r*66 + w)*144 + c*2;
        *(__nv_bfloat16*)(smc + P_HI + off) = hi;
        *(__nv_bfloat16*)(smc + P_LO + off) = lo;
    }
    cpa_wait0();
    __syncthreads();

    float acc[4][4][4];
    #pragma unroll
    for (int mi = 0; mi < 4; ++mi)
        #pragma unroll
        for (int ni = 0; ni < 4; ++ni)
            #pragma unroll
            for (int k = 0; k < 4; ++k) acc[mi][ni][k] = 0.f;

    int lane15 = l & 15;
    int kh8 = ((l >> 4) & 1) * 8;
    int noff = ((l >> 4) & 1) * 8;

    for (int q = 0; q < 9; ++q) {
        int kh = q / 3, kw = q - kh*3;
        uint32_t bwbase = sb + BW0;
        int prow0 = ((warp_m + kh)*66 + kw) * 144;

        #pragma unroll
        for (int ks = 0; ks < 4; ++ks) {
            int k0 = ks * 16;
            uint32_t aH[4][4], aL[4][4];
            #pragma unroll
            for (int mi = 0; mi < 4; ++mi) {
                uint32_t off = (uint32_t)(prow0 + (mi*16 + lane15)*144 + (k0 + kh8)*2);
                ldsm4(aH[mi], sb + P_HI + off);
                ldsm4(aL[mi], sb + P_LO + off);
            }
            uint32_t bH[2][4], bL[2][4];
            #pragma unroll
            for (int n2 = 0; n2 < 2; ++n2) {
                uint32_t boff = (uint32_t)((k0 + lane15)*272 + (warp_n*32 + n2*16 + noff)*2);
                ldsm4t(bH[n2], bwbase + boff);
                ldsm4t(bL[n2], bwbase + 17408 + boff);
            }
            #pragma unroll
            for (int mi = 0; mi < 4; ++mi)
                #pragma unroll
                for (int ni = 0; ni < 4; ++ni) {
                    const uint32_t* bh = &bH[ni >> 1][(ni & 1)*2];
                    const uint32_t* bl = &bL[ni >> 1][(ni & 1)*2];
                    mma16816(acc[mi][ni], aH[mi], bh);
                    mma16816(acc[mi][ni], aH[mi], bl);
                    mma16816(acc[mi][ni], aL[mi], bh);
                }
        }

        __syncthreads();    // all warps done reading BW0 before overwrite
        if (q < 8) {
            const unsigned char* src = g_wB + (size_t)(q + 1)*34816;
            for (int i = t; i < 2176; i += 256)
                cpa16(sb + BW0 + i*16, src + i*16);
            cpa_commit();
            cpa_wait0();
            __syncthreads();
        }
    }

    __syncthreads();
    float* D = (float*)smc;
    #pragma unroll
    for (int mi = 0; mi < 4; ++mi)
        #pragma unroll
        for (int ni = 0; ni < 4; ++ni) {
            int px = warp_m*64 + mi*16 + (l >> 2);
            int o  = warp_n*32 + ni*8 + 2*(l & 3);
            D[o*130 + px]           = acc[mi][ni][0];
            D[(o + 1)*130 + px]     = acc[mi][ni][1];
            D[o*130 + px + 8]       = acc[mi][ni][2];
            D[(o + 1)*130 + px + 8] = acc[mi][ni][3];
        }
    __syncthreads();

    int wp = t & 63, og = t >> 6;
    #pragma unroll
    for (int r = 0; r < 2; ++r) {
        int h = h0 + r;
        int wg = w0 + wp;
        float rt = g_ratio[((size_t)b*HH0 + h)*WW0 + wg];
        #pragma unroll 8
        for (int oo = 0; oo < 32; ++oo) {
            int o = oo*4 + og;
            float v = D[o*130 + r*64 + wp];
            g_y[(((size_t)b*CO + o)*HH0 + h)*WW0 + wg] = (rt > 0.f) ? v*rt + bias[o] : 0.f;
        }
    }
}

// ---------------- K3: GDN (in-place), scalar GEMM, vectorized smem/gmem (R11 proven) --
__global__ void __launch_bounds__(256) k_gdn(const float* __restrict__ gamma,
                                             const float* __restrict__ beta) {
    __shared__ float zs[16][128];
    __shared__ float gsT[16][132];   // [k][o], row pad 132 (16B aligned)

    size_t p0 = (size_t)blockIdx.x * 128;
    int b   = (int)(p0 >> 16);
    int hw0 = (int)(p0 & 65535);
    int t = threadIdx.x;
    int px = t & 15, oy = t >> 4;

    float acc[8][8];
    #pragma unroll
    for (int i = 0; i < 8; ++i)
        #pragma unroll
        for (int j = 0; j < 8; ++j) acc[i][j] = 0.f;

    float* yb = g_y + (size_t)b*CO*HWSZ + hw0;

    for (int c0 = 0; c0 < CO; c0 += 16) {
        __syncthreads();
        for (int i = t; i < 2048; i += 256) {        // z = x^2 chunk [16][128]
            int k = i >> 7, p = i & 127;
            float v = yb[(size_t)(c0 + k)*HWSZ + p];
            zs[k][p] = v*v;
        }
        for (int i = t; i < 2048; i += 256) {        // gamma chunk transposed [k][o]
            int o = i >> 4, k = i & 15;
            gsT[k][o] = gamma[o*CO + c0 + k];
        }
        __syncthreads();
        #pragma unroll
        for (int k = 0; k < 16; ++k) {
            float4 a0 = *(const float4*)&gsT[k][oy*8];
            float4 a1 = *(const float4*)&gsT[k][oy*8 + 4];
            float4 b0 = *(const float4*)&zs[k][px*8];
            float4 b1 = *(const float4*)&zs[k][px*8 + 4];
            float a[8] = {a0.x, a0.y, a0.z, a0.w, a1.x, a1.y, a1.z, a1.w};
            float bb[8] = {b0.x, b0.y, b0.z, b0.w, b1.x, b1.y, b1.z, b1.w};
            #pragma unroll
            for (int i = 0; i < 8; ++i)
                #pragma unroll
                for (int j = 0; j < 8; ++j) acc[i][j] += a[i]*bb[j];
        }
    }

    float4 m0 = *(const float4*)&g_mvalid[p0 + px*8];
    float4 m1 = *(const float4*)&g_mvalid[p0 + px*8 + 4];
    float mv[8] = {m0.x, m0.y, m0.z, m0.w, m1.x, m1.y, m1.z, m1.w};
    #pragma unroll
    for (int i = 0; i < 8; ++i) {
        int o = oy*8 + i;
        float bo = beta[o];
        size_t ad = (size_t)o*HWSZ + px*8;
        float4 x0 = *(const float4*)&yb[ad];
        float4 x1 = *(const float4*)&yb[ad + 4];
        float xv[8] = {x0.x, x0.y, x0.z, x0.w, x1.x, x1.y, x1.z, x1.w};
        float4 r0, r1;
        r0.x = xv[0] * rsqrtf(bo + acc[i][0]) * mv[0];
        r0.y = xv[1] * rsqrtf(bo + acc[i][1]) * mv[1];
        r0.z = xv[2] * rsqrtf(bo + acc[i][2]) * mv[2];
        r0.w = xv[3] * rsqrtf(bo + acc[i][3]) * mv[3];
        r1.x = xv[4] * rsqrtf(bo + acc[i][4]) * mv[4];
        r1.y = xv[5] * rsqrtf(bo + acc[i][5]) * mv[5];
        r1.z = xv[6] * rsqrtf(bo + acc[i][6]) * mv[6];
        r1.w = xv[7] * rsqrtf(bo + acc[i][7]) * mv[7];
        *(float4*)&yb[ad]     = r0;
        *(float4*)&yb[ad + 4] = r1;
    }
}

// ---------------- K4: fused DWT (rows + cols in one pass) -> 4 bands ----------------
#define DX_OFS 0          // xs[39][256] floats
#define DL_OFS 9984       // lo[16][260]
#define DH_OFS 14144      // hi[16][260]
#define SMEM_DWT 73216    // 18304 floats

__global__ void __launch_bounds__(256) k_dwt_fused(float* __restrict__ out) {
    float* sm = (float*)smc;
    float* xs = sm + DX_OFS;
    float* lo = sm + DL_OFS;
    float* hi = sm + DH_OFS;

    int t = threadIdx.x;
    int hr0 = blockIdx.x * 16;
    int bc  = blockIdx.y;
    const float* img = g_y + (size_t)bc*HWSZ;

    for (int i = t; i < 9984; i += 256) {
        int r = i >> 8, w = i & 255;
        int h = refl(2*hr0 - 4 + r, HH0);
        xs[r*256 + w] = img[h*WW0 + w];
    }
    __syncthreads();

    {
        int w = t;
        #pragma unroll 4
        for (int d = 0; d < 16; ++d) {
            const float* col = xs + 2*d*256 + w;
            float a0 = col[0],      a1 = col[256],  a2 = col[512],  a3 = col[768];
            float a4 = col[1024],   a5 = col[1280], a6 = col[1536], a7 = col[1792];
            float a8 = col[2048];
            float lv = c_H0[0]*a0 + c_H0[1]*a1 + c_H0[2]*a2 + c_H0[3]*a3 + c_H0[4]*a4
                     + c_H0[5]*a5 + c_H0[6]*a6 + c_H0[7]*a7 + c_H0[8]*a8;
            float hv = c_H1[0]*a1 + c_H1[1]*a2 + c_H1[2]*a3 + c_H1[3]*a4
                     + c_H1[4]*a5 + c_H1[5]*a6 + c_H1[6]*a7;
            lo[d*260 + w] = lv;
            hi[d*260 + w] = hv;
        }
    }
    __syncthreads();

    size_t obase = (size_t)bc*HD*WD;
    for (int i = t; i < 2048; i += 256) {
        int wr = i & 127, d = i >> 7;
        const float* lrow = lo + d*260;
        const float* hrow = hi + d*260;
        float rl[9], rh[9];
        #pragma unroll
        for (int k = 0; k < 9; ++k) {
            int j = refl(2*wr + k - 4, WW0);
            rl[k] = lrow[j];
            rh[k] = hrow[j];
        }
        float ll = 0.f, lh = 0.f, hl = 0.f, hh = 0.f;
        #pragma unroll
        for (int k = 0; k < 9; ++k) { ll += c_H0[k]*rl[k]; hl += c_H0[k]*rh[k]; }
        #pragma unroll
        for (int k = 0; k < 7; ++k) { lh += c_H1[k]*rl[k+1]; hh += c_H1[k]*rh[k+1]; }
        size_t oidx = obase + (size_t)(hr0 + d)*WD + wr;
        out[OFS_LL + oidx] = ll;
        out[OFS_LH + oidx] = lh;
        out[OFS_HL + oidx] = hl;
        out[OFS_HH + oidx] = hh;
    }
}

// ---------------- K5: fused mask downsample (H + W in one pass) -> 4 mask bands ------
// CTA = one batch image x 16 output rows. smem: ms[39][256] + mlo/mhi[16][256].
#define MK_X   0
#define MK_LO  9984
#define MK_HI  14080
#define SMEM_MASK 72704

__global__ void __launch_bounds__(256) k_mask_fused(float* __restrict__ out) {
    float* sm  = (float*)smc;
    float* ms  = sm + MK_X;     // [39][256]
    float* mlo = sm + MK_LO;    // [16][256]
    float* mhi = sm + MK_HI;    // [16][256]

    int t = threadIdx.x;
    int hr0 = blockIdx.x * 16;
    int b   = blockIdx.y;
    const float* mv = g_mvalid + (size_t)b*HWSZ;

    for (int i = t; i < 9984; i += 256) {
        int r = i >> 8, w = i & 255;
        int h = refl(2*hr0 - 4 + r, HH0);
        ms[r*256 + w] = mv[h*WW0 + w];
    }
    __syncthreads();

    {
        int w = t;
        #pragma unroll 4
        for (int d = 0; d < 16; ++d) {
            const float* col = ms + 2*d*256 + w;
            float s9 = 0.f, s7 = 0.f;
            #pragma unroll
            for (int k = 0; k < 9; ++k) {
                float v = col[k*256];
                s9 += v;
                if (k >= 1 && k <= 7) s7 += v;
            }
            mlo[d*256 + w] = (s9 > 0.f) ? 1.f : 0.f;
            mhi[d*256 + w] = (s7 > 0.f) ? 1.f : 0.f;
        }
    }
    __syncthreads();

    size_t obase = (size_t)b*HD*WD;
    for (int i = t; i < 2048; i += 256) {
        int wr = i & 127, d = i >> 7;
        const float* lrow = mlo + d*256;
        const float* hrow = mhi + d*256;
        float s9l = 0.f, s7l = 0.f, s9h = 0.f, s7h = 0.f;
        #pragma unroll
        for (int k = 0; k < 9; ++k) {
            int j = refl(2*wr + k - 4, WW0);
            float vl = lrow[j], vh = hrow[j];
            s9l += vl; s9h += vh;
            if (k >= 1 && k <= 7) { s7l += vl; s7h += vh; }
        }
        size_t oidx = obase + (size_t)(hr0 + d)*WD + wr;
        out[OFS_MLL + oidx] = (s9l > 0.f) ? 1.f : 0.f;
        out[OFS_MLH + oidx] = (s7l > 0.f) ? 1.f : 0.f;
        out[OFS_MHL + oidx] = (s9h > 0.f) ? 1.f : 0.f;
        out[OFS_MHH + oidx] = (s7h > 0.f) ? 1.f : 0.f;
    }
}

// ---------------- launch ----------------
extern "C" void kernel_launch(void* const* d_in, const int* in_sizes, int n_in,
                              void* d_out, int out_size) {
    const float* tensor = (const float*)d_in[0];
    const float* mask   = (const float*)d_in[1];
    const float* weight = (const float*)d_in[2];
    const float* bias   = (const float*)d_in[3];
    const float* u      = (const float*)d_in[4];
    const float* beta   = (const float*)d_in[5];
    const float* gamma  = (const float*)d_in[6];
    float* out = (float*)d_out;

    cudaFuncSetAttribute(k_conv_mma, cudaFuncAttributeMaxDynamicSharedMemorySize, SMEM_MMA);
    cudaFuncSetAttribute(k_dwt_fused, cudaFuncAttributeMaxDynamicSharedMemorySize, SMEM_DWT);
    cudaFuncSetAttribute(k_mask_fused, cudaFuncAttributeMaxDynamicSharedMemorySize, SMEM_MASK);

    k_sigma<<<1, 576>>>(weight, u);
    k_prepw<<<288, 256>>>();
    k_ratio<<<(NB*HWSZ)/256, 256>>>(mask);
    k_conv_mma<<<dim3(4, 128, NB), 256, SMEM_MMA>>>(tensor, mask, bias);
    k_gdn<<<(NB*HWSZ)/128, 256>>>(gamma, beta);
    k_dwt_fused<<<dim3(8, NB*CO), 256, SMEM_DWT>>>(out);
    k_mask_fused<<<dim3(8, NB), 256, SMEM_MASK>>>(out);
}

// round 14
// speedup vs baseline: 1.6133x; 1.0700x over previous
#include <cuda_runtime.h>
#include <cuda_bf16.h>
#include <math.h>
#include <stdint.h>

#define NB   8
#define CIN  64
#define CO   128
#define HH0  256
#define WW0  256
#define HWSZ 65536
#define HD   128
#define WD   128

// ---------------- scratch ----------------
__device__ float g_wsn[CO*CIN*9];
__device__ unsigned char g_wB[9*34816];     // per-tap [hi|lo][64 c-rows x 272B (128 o bf16 + pad)]
__device__ unsigned char g_gB2[98304];      // gamma chunks: [ks:8][hi|lo][128 o x 48B]
__device__ float g_ratio[NB*HWSZ];
__device__ float g_mvalid[NB*HWSZ];
__device__ float g_y[(size_t)NB*CO*HWSZ];

__constant__ float c_H0[9] = {
    0.026748757410810f, -0.016864118442875f, -0.078223266528990f,
    0.266864118442875f,  0.602949018236360f,  0.266864118442875f,
   -0.078223266528990f, -0.016864118442875f,  0.026748757410810f};
__constant__ float c_H1[7] = {
    0.091271763114250f, -0.057543526228500f, -0.591271763114250f,
    1.115087052457000f, -0.591271763114250f, -0.057543526228500f,
    0.091271763114250f};

#define SZ_BAND ((size_t)NB*CO*HD*WD)
#define SZ_MASK ((size_t)NB*HD*WD)
#define OFS_LL   ((size_t)0)
#define OFS_MLL  (OFS_LL  + SZ_BAND)
#define OFS_LH   (OFS_MLL + SZ_MASK)
#define OFS_HL   (OFS_LH  + SZ_BAND)
#define OFS_HH   (OFS_HL  + SZ_BAND)
#define OFS_MLH  (OFS_HH  + SZ_BAND)
#define OFS_MHL  (OFS_MLH + SZ_MASK)
#define OFS_MHH  (OFS_MHL + SZ_MASK)

__device__ __forceinline__ int refl(int j, int n) {
    if (j < 0) j = -j;
    if (j >= n) j = 2*n - 2 - j;
    return j;
}

// ---------------- mma.sync / ldmatrix / cp.async helpers (baseline PTX, sm_80+) ----------
__device__ __forceinline__ uint32_t smem_u32(const void* p) {
    uint32_t a;
    asm("{ .reg .u64 t; cvta.to.shared.u64 t, %1; cvt.u32.u64 %0, t; }" : "=r"(a) : "l"(p));
    return a;
}
__device__ __forceinline__ void ldsm4(uint32_t* r, uint32_t a) {
    asm volatile("ldmatrix.sync.aligned.m8n8.x4.shared.b16 {%0,%1,%2,%3}, [%4];"
        : "=r"(r[0]), "=r"(r[1]), "=r"(r[2]), "=r"(r[3]) : "r"(a));
}
__device__ __forceinline__ void ldsm4t(uint32_t* r, uint32_t a) {
    asm volatile("ldmatrix.sync.aligned.m8n8.x4.trans.shared.b16 {%0,%1,%2,%3}, [%4];"
        : "=r"(r[0]), "=r"(r[1]), "=r"(r[2]), "=r"(r[3]) : "r"(a));
}
__device__ __forceinline__ void mma16816(float* c, const uint32_t* a, const uint32_t* b) {
    asm volatile("mma.sync.aligned.m16n8k16.row.col.f32.bf16.bf16.f32 "
        "{%0,%1,%2,%3},{%4,%5,%6,%7},{%8,%9},{%0,%1,%2,%3};"
        : "+f"(c[0]), "+f"(c[1]), "+f"(c[2]), "+f"(c[3])
        : "r"(a[0]), "r"(a[1]), "r"(a[2]), "r"(a[3]), "r"(b[0]), "r"(b[1]));
}
__device__ __forceinline__ void cpa16(uint32_t s, const void* g) {
    asm volatile("cp.async.cg.shared.global [%0], [%1], 16;" :: "r"(s), "l"(g) : "memory");
}
__device__ __forceinline__ void cpa_commit() {
    asm volatile("cp.async.commit_group;" ::: "memory");
}
__device__ __forceinline__ void cpa_wait0() {
    asm volatile("cp.async.wait_group 0;" ::: "memory");
}

// ---------------- K0: spectral norm -> g_wsn ----------------
__global__ void k_sigma(const float* __restrict__ w, const float* __restrict__ u) {
    __shared__ float sv[576];
    __shared__ float red[576];
    __shared__ float s_bcast;
    int t = threadIdx.x;

    float vj = 0.f;
    for (int o = 0; o < CO; ++o) vj += w[o*576 + t] * u[o];
    red[t] = vj*vj;
    sv[t] = vj;
    __syncthreads();
    if (t == 0) {
        float s = 0.f;
        for (int i = 0; i < 576; ++i) s += red[i];
        s_bcast = 1.f / (sqrtf(s) + 1e-12f);
    }
    __syncthreads();
    float vn = sv[t] * s_bcast;
    __syncthreads();
    sv[t] = vn;
    __syncthreads();

    if (t < CO) {
        float s = 0.f;
        for (int j = 0; j < 576; ++j) s += w[t*576 + j] * sv[j];
        red[t] = s*s;
    }
    __syncthreads();
    if (t == 0) {
        float s = 0.f;
        for (int i = 0; i < CO; ++i) s += red[i];
        s_bcast = 1.f / sqrtf(s);
    }
    __syncthreads();
    float inv_sigma = s_bcast;
    for (int i = t; i < CO*CIN*9; i += 576) g_wsn[i] = w[i] * inv_sigma;
}

// ---------------- K0b: weights -> per-tap [c][o] bf16 hi/lo rows (272B stride) --------
__global__ void k_prepw() {
    int idx = blockIdx.x*256 + threadIdx.x;
    if (idx >= 9*CIN*CO) return;
    int q = idx >> 13;
    int rem = idx & 8191;
    int c = rem >> 7;
    int o = rem & 127;
    float v = g_wsn[(o*CIN + c)*9 + q];
    __nv_bfloat16 hi = __float2bfloat16(v);
    __nv_bfloat16 lo = __float2bfloat16(v - __bfloat162float(hi));
    size_t base = (size_t)q*34816;
    *(__nv_bfloat16*)(g_wB + base +         c*272 + o*2) = hi;
    *(__nv_bfloat16*)(g_wB + base + 17408 + c*272 + o*2) = lo;
}

// ---------------- K0c: gamma -> 8 chunks [hi|lo][128 o][48B] (16 c per chunk) --------
__global__ void k_prepg(const float* __restrict__ gamma) {
    int idx = blockIdx.x*256 + threadIdx.x;   // 16384 = 8ks * 128o * 16k
    if (idx >= 8*128*16) return;
    int ks = idx >> 11;
    int o  = (idx >> 4) & 127;
    int k  = idx & 15;
    float v = gamma[o*CO + ks*16 + k];
    __nv_bfloat16 hi = __float2bfloat16(v);
    __nv_bfloat16 lo = __float2bfloat16(v - __bfloat162float(hi));
    *(__nv_bfloat16*)(g_gB2 + ks*12288 +        o*48 + k*2) = hi;
    *(__nv_bfloat16*)(g_gB2 + ks*12288 + 6144 + o*48 + k*2) = lo;
}

// ---------------- K1: mask 3x3 box -> ratio + valid ----------------
__global__ void k_ratio(const float* __restrict__ mask) {
    int idx = blockIdx.x*256 + threadIdx.x;
    int b = idx >> 16;
    int hw = idx & 65535;
    int h = hw >> 8, wx = hw & 255;
    const float* mb = mask + (size_t)b*HWSZ;
    float s = 0.f;
    #pragma unroll
    for (int dh = -1; dh <= 1; ++dh) {
        int h2 = h + dh;
        if (h2 < 0 || h2 >= HH0) continue;
        #pragma unroll
        for (int dw = -1; dw <= 1; ++dw) {
            int w2 = wx + dw;
            if (w2 < 0 || w2 >= WW0) continue;
            s += mb[h2*WW0 + w2];
        }
    }
    bool valid = s > 0.f;
    g_mvalid[idx] = valid ? 1.f : 0.f;
    g_ratio[idx]  = valid ? 9.f / fmaxf(s, 1e-8f) : 0.f;
}

// ---------------- K2: mma.sync implicit-GEMM conv (bf16 3-term split) ----------------
// Single-buffered weights -> smem 110848 -> 2 CTAs/SM.
#define P_HI 0
#define P_LO 38016
#define BW0  76032
#define SMEM_MMA 110848

extern __shared__ char smc[];

__global__ void __launch_bounds__(256, 2) k_conv_mma(const float* __restrict__ x,
                                                     const float* __restrict__ mask,
                                                     const float* __restrict__ bias) {
    uint32_t sb = smem_u32(smc);
    int t = threadIdx.x, l = t & 31, wid = t >> 5;
    int w0 = blockIdx.x * 64, h0 = blockIdx.y * 2, b = blockIdx.z;
    int warp_m = wid & 1;
    int warp_n = wid >> 1;

    // prefetch tap 0
    for (int i = t; i < 2176; i += 256)
        cpa16(sb + BW0 + i*16, g_wB + i*16);
    cpa_commit();

    // patch fill: 64c x 4rows x 66w of (x*mask), bf16 hi/lo
    for (int i = t; i < 16896; i += 256) {
        int w = i % 66;
        int rem = i / 66;
        int r = rem & 3;
        int c = rem >> 2;
        int h = h0 - 1 + r, wx = w0 - 1 + w;
        float v = 0.f;
        if (h >= 0 && h < HH0 && wx >= 0 && wx < WW0)
            v = x[(((size_t)b*CIN + c)*HH0 + h)*WW0 + wx]
              * mask[((size_t)b*HH0 + h)*WW0 + wx];
        __nv_bfloat16 hi = __float2bfloat16(v);
        __nv_bfloat16 lo = __float2bfloat16(v - __bfloat162float(hi));
        int off = (r*66 + w)*144 + c*2;
        *(__nv_bfloat16*)(smc + P_HI + off) = hi;
        *(__nv_bfloat16*)(smc + P_LO + off) = lo;
    }
    cpa_wait0();
    __syncthreads();

    float acc[4][4][4];
    #pragma unroll
    for (int mi = 0; mi < 4; ++mi)
        #pragma unroll
        for (int ni = 0; ni < 4; ++ni)
            #pragma unroll
            for (int k = 0; k < 4; ++k) acc[mi][ni][k] = 0.f;

    int lane15 = l & 15;
    int kh8 = ((l >> 4) & 1) * 8;
    int noff = ((l >> 4) & 1) * 8;

    for (int q = 0; q < 9; ++q) {
        int kh = q / 3, kw = q - kh*3;
        uint32_t bwbase = sb + BW0;
        int prow0 = ((warp_m + kh)*66 + kw) * 144;

        #pragma unroll
        for (int ks = 0; ks < 4; ++ks) {
            int k0 = ks * 16;
            uint32_t aH[4][4], aL[4][4];
            #pragma unroll
            for (int mi = 0; mi < 4; ++mi) {
                uint32_t off = (uint32_t)(prow0 + (mi*16 + lane15)*144 + (k0 + kh8)*2);
                ldsm4(aH[mi], sb + P_HI + off);
                ldsm4(aL[mi], sb + P_LO + off);
            }
            uint32_t bH[2][4], bL[2][4];
            #pragma unroll
            for (int n2 = 0; n2 < 2; ++n2) {
                uint32_t boff = (uint32_t)((k0 + lane15)*272 + (warp_n*32 + n2*16 + noff)*2);
                ldsm4t(bH[n2], bwbase + boff);
                ldsm4t(bL[n2], bwbase + 17408 + boff);
            }
            #pragma unroll
            for (int mi = 0; mi < 4; ++mi)
                #pragma unroll
                for (int ni = 0; ni < 4; ++ni) {
                    const uint32_t* bh = &bH[ni >> 1][(ni & 1)*2];
                    const uint32_t* bl = &bL[ni >> 1][(ni & 1)*2];
                    mma16816(acc[mi][ni], aH[mi], bh);
                    mma16816(acc[mi][ni], aH[mi], bl);
                    mma16816(acc[mi][ni], aL[mi], bh);
                }
        }

        __syncthreads();    // all warps done reading BW0 before overwrite
        if (q < 8) {
            const unsigned char* src = g_wB + (size_t)(q + 1)*34816;
            for (int i = t; i < 2176; i += 256)
                cpa16(sb + BW0 + i*16, src + i*16);
            cpa_commit();
            cpa_wait0();
            __syncthreads();
        }
    }

    __syncthreads();
    float* D = (float*)smc;
    #pragma unroll
    for (int mi = 0; mi < 4; ++mi)
        #pragma unroll
        for (int ni = 0; ni < 4; ++ni) {
            int px = warp_m*64 + mi*16 + (l >> 2);
            int o  = warp_n*32 + ni*8 + 2*(l & 3);
            D[o*130 + px]           = acc[mi][ni][0];
            D[(o + 1)*130 + px]     = acc[mi][ni][1];
            D[o*130 + px + 8]       = acc[mi][ni][2];
            D[(o + 1)*130 + px + 8] = acc[mi][ni][3];
        }
    __syncthreads();

    int wp = t & 63, og = t >> 6;
    #pragma unroll
    for (int r = 0; r < 2; ++r) {
        int h = h0 + r;
        int wg = w0 + wp;
        float rt = g_ratio[((size_t)b*HH0 + h)*WW0 + wg];
        #pragma unroll 8
        for (int oo = 0; oo < 32; ++oo) {
            int o = oo*4 + og;
            float v = D[o*130 + r*64 + wp];
            g_y[(((size_t)b*CO + o)*HH0 + h)*WW0 + wg] = (rt > 0.f) ? v*rt + bias[o] : 0.f;
        }
    }
}

// ---------------- K3: GDN via mma.sync, chunked gamma -> 2 CTAs/SM ----------------
// M = 128 o (gamma chunks, ldsm4, 48B rows), N = 128 px (z = y^2, ldsm4t, 272B rows),
// K = 128 c in 8 chunks of 16. gamma double-buffered via cp.async. In-place on g_y.
#define GZ_HI  0
#define GZ_LO  34816
#define GB_OFS 69632          // 2 x 12288 gamma chunk buffers
#define SMEM_GDN 94208
#define S_OFS  0              // s[o:128][130] f32 overlays z after mma

__global__ void __launch_bounds__(256, 2) k_gdn_mma(const float* __restrict__ beta) {
    uint32_t sb = smem_u32(smc);
    int t = threadIdx.x, l = t & 31, wid = t >> 5;
    int warp_m = wid & 1;          // o half (64 each)
    int warp_n = wid >> 1;         // px quarter (32 each)

    size_t p0 = (size_t)blockIdx.x * 128;
    int b   = (int)(p0 >> 16);
    int hw0 = (int)(p0 & 65535);
    float* yb = g_y + (size_t)b*CO*HWSZ + hw0;

    // prefetch gamma chunk 0
    for (int i = t; i < 768; i += 256)
        cpa16(sb + GB_OFS + i*16, g_gB2 + i*16);
    cpa_commit();

    // stage z = y^2 as [c rows][128 px] bf16 hi/lo, 272B stride
    for (int i = t; i < 16384; i += 256) {
        int c = i >> 7, p = i & 127;
        float v = yb[(size_t)c*HWSZ + p];
        v *= v;
        __nv_bfloat16 hi = __float2bfloat16(v);
        __nv_bfloat16 lo = __float2bfloat16(v - __bfloat162float(hi));
        int off = c*272 + p*2;
        *(__nv_bfloat16*)(smc + GZ_HI + off) = hi;
        *(__nv_bfloat16*)(smc + GZ_LO + off) = lo;
    }
    cpa_wait0();
    __syncthreads();

    float sacc[4][4][4];
    #pragma unroll
    for (int mi = 0; mi < 4; ++mi)
        #pragma unroll
        for (int ni = 0; ni < 4; ++ni)
            #pragma unroll
            for (int k = 0; k < 4; ++k) sacc[mi][ni][k] = 0.f;

    int lane15 = l & 15;
    int kh8 = ((l >> 4) & 1) * 8;
    int noff = ((l >> 4) & 1) * 8;

    for (int ks = 0; ks < 8; ++ks) {
        // prefetch next gamma chunk into the other buffer
        if (ks < 7) {
            uint32_t dst = sb + GB_OFS + ((ks + 1) & 1)*12288;
            const unsigned char* src = g_gB2 + (ks + 1)*12288;
            for (int i = t; i < 768; i += 256)
                cpa16(dst + i*16, src + i*16);
        }
        cpa_commit();

        int k0 = ks * 16;
        uint32_t gbuf = sb + GB_OFS + (ks & 1)*12288;
        uint32_t aH[4][4], aL[4][4];
        #pragma unroll
        for (int mi = 0; mi < 4; ++mi) {
            uint32_t off = (uint32_t)((warp_m*64 + mi*16 + lane15)*48 + kh8*2);
            ldsm4(aH[mi], gbuf + off);
            ldsm4(aL[mi], gbuf + 6144 + off);
        }
        uint32_t bH[2][4], bL[2][4];
        #pragma unroll
        for (int n2 = 0; n2 < 2; ++n2) {
            uint32_t boff = (uint32_t)((k0 + lane15)*272 + (warp_n*32 + n2*16 + noff)*2);
            ldsm4t(bH[n2], sb + GZ_HI + boff);
            ldsm4t(bL[n2], sb + GZ_LO + boff);
        }
        #pragma unroll
        for (int mi = 0; mi < 4; ++mi)
            #pragma unroll
            for (int ni = 0; ni < 4; ++ni) {
                const uint32_t* bh = &bH[ni >> 1][(ni & 1)*2];
                const uint32_t* bl = &bL[ni >> 1][(ni & 1)*2];
                mma16816(sacc[mi][ni], aH[mi], bh);
                mma16816(sacc[mi][ni], aH[mi], bl);
                mma16816(sacc[mi][ni], aL[mi], bh);
            }

        cpa_wait0();
        __syncthreads();
    }

    // s frags -> S[o][130] (overlays z)
    float* S = (float*)(smc + S_OFS);
    #pragma unroll
    for (int mi = 0; mi < 4; ++mi)
        #pragma unroll
        for (int ni = 0; ni < 4; ++ni) {
            int o  = warp_m*64 + mi*16 + (l >> 2);
            int px = warp_n*32 + ni*8 + 2*(l & 3);
            S[o*130 + px]           = sacc[mi][ni][0];
            S[o*130 + px + 1]       = sacc[mi][ni][1];
            S[(o + 8)*130 + px]     = sacc[mi][ni][2];
            S[(o + 8)*130 + px + 1] = sacc[mi][ni][3];
        }
    __syncthreads();

    // final: y = y * rsqrt(beta + s) * mask, coalesced
    int px = t & 127, og = t >> 7;
    float mvv = g_mvalid[p0 + px];
    #pragma unroll 16
    for (int oo = 0; oo < 64; ++oo) {
        int o = oo*2 + og;
        float s = S[o*130 + px];
        size_t ad = (size_t)o*HWSZ + px;
        float xv = yb[ad];
        yb[ad] = xv * rsqrtf(beta[o] + s) * mvv;
    }
}

// ---------------- K4: fused DWT (rows + cols in one pass) -> 4 bands ----------------
#define DX_OFS 0          // xs[39][256] floats
#define DL_OFS 9984       // lo[16][260]
#define DH_OFS 14144      // hi[16][260]
#define SMEM_DWT 73216    // 18304 floats

__global__ void __launch_bounds__(256) k_dwt_fused(float* __restrict__ out) {
    float* sm = (float*)smc;
    float* xs = sm + DX_OFS;
    float* lo = sm + DL_OFS;
    float* hi = sm + DH_OFS;

    int t = threadIdx.x;
    int hr0 = blockIdx.x * 16;
    int bc  = blockIdx.y;
    const float* img = g_y + (size_t)bc*HWSZ;

    for (int i = t; i < 9984; i += 256) {
        int r = i >> 8, w = i & 255;
        int h = refl(2*hr0 - 4 + r, HH0);
        xs[r*256 + w] = img[h*WW0 + w];
    }
    __syncthreads();

    {
        int w = t;
        #pragma unroll 4
        for (int d = 0; d < 16; ++d) {
            const float* col = xs + 2*d*256 + w;
            float a0 = col[0],      a1 = col[256],  a2 = col[512],  a3 = col[768];
            float a4 = col[1024],   a5 = col[1280], a6 = col[1536], a7 = col[1792];
            float a8 = col[2048];
            float lv = c_H0[0]*a0 + c_H0[1]*a1 + c_H0[2]*a2 + c_H0[3]*a3 + c_H0[4]*a4
                     + c_H0[5]*a5 + c_H0[6]*a6 + c_H0[7]*a7 + c_H0[8]*a8;
            float hv = c_H1[0]*a1 + c_H1[1]*a2 + c_H1[2]*a3 + c_H1[3]*a4
                     + c_H1[4]*a5 + c_H1[5]*a6 + c_H1[6]*a7;
            lo[d*260 + w] = lv;
            hi[d*260 + w] = hv;
        }
    }
    __syncthreads();

    size_t obase = (size_t)bc*HD*WD;
    for (int i = t; i < 2048; i += 256) {
        int wr = i & 127, d = i >> 7;
        const float* lrow = lo + d*260;
        const float* hrow = hi + d*260;
        float rl[9], rh[9];
        #pragma unroll
        for (int k = 0; k < 9; ++k) {
            int j = refl(2*wr + k - 4, WW0);
            rl[k] = lrow[j];
            rh[k] = hrow[j];
        }
        float ll = 0.f, lh = 0.f, hl = 0.f, hh = 0.f;
        #pragma unroll
        for (int k = 0; k < 9; ++k) { ll += c_H0[k]*rl[k]; hl += c_H0[k]*rh[k]; }
        #pragma unroll
        for (int k = 0; k < 7; ++k) { lh += c_H1[k]*rl[k+1]; hh += c_H1[k]*rh[k+1]; }
        size_t oidx = obase + (size_t)(hr0 + d)*WD + wr;
        out[OFS_LL + oidx] = ll;
        out[OFS_LH + oidx] = lh;
        out[OFS_HL + oidx] = hl;
        out[OFS_HH + oidx] = hh;
    }
}

// ---------------- K5: fused mask downsample (H + W in one pass) -> 4 mask bands ------
#define MK_X   0
#define MK_LO  9984
#define MK_HI  14080
#define SMEM_MASK 72704

__global__ void __launch_bounds__(256) k_mask_fused(float* __restrict__ out) {
    float* sm  = (float*)smc;
    float* ms  = sm + MK_X;     // [39][256]
    float* mlo = sm + MK_LO;    // [16][256]
    float* mhi = sm + MK_HI;    // [16][256]

    int t = threadIdx.x;
    int hr0 = blockIdx.x * 16;
    int b   = blockIdx.y;
    const float* mv = g_mvalid + (size_t)b*HWSZ;

    for (int i = t; i < 9984; i += 256) {
        int r = i >> 8, w = i & 255;
        int h = refl(2*hr0 - 4 + r, HH0);
        ms[r*256 + w] = mv[h*WW0 + w];
    }
    __syncthreads();

    {
        int w = t;
        #pragma unroll 4
        for (int d = 0; d < 16; ++d) {
            const float* col = ms + 2*d*256 + w;
            float s9 = 0.f, s7 = 0.f;
            #pragma unroll
            for (int k = 0; k < 9; ++k) {
                float v = col[k*256];
                s9 += v;
                if (k >= 1 && k <= 7) s7 += v;
            }
            mlo[d*256 + w] = (s9 > 0.f) ? 1.f : 0.f;
            mhi[d*256 + w] = (s7 > 0.f) ? 1.f : 0.f;
        }
    }
    __syncthreads();

    size_t obase = (size_t)b*HD*WD;
    for (int i = t; i < 2048; i += 256) {
        int wr = i & 127, d = i >> 7;
        const float* lrow = mlo + d*256;
        const float* hrow = mhi + d*256;
        float s9l = 0.f, s7l = 0.f, s9h = 0.f, s7h = 0.f;
        #pragma unroll
        for (int k = 0; k < 9; ++k) {
            int j = refl(2*wr + k - 4, WW0);
            float vl = lrow[j], vh = hrow[j];
            s9l += vl; s9h += vh;
            if (k >= 1 && k <= 7) { s7l += vl; s7h += vh; }
        }
        size_t oidx = obase + (size_t)(hr0 + d)*WD + wr;
        out[OFS_MLL + oidx] = (s9l > 0.f) ? 1.f : 0.f;
        out[OFS_MLH + oidx] = (s7l > 0.f) ? 1.f : 0.f;
        out[OFS_MHL + oidx] = (s9h > 0.f) ? 1.f : 0.f;
        out[OFS_MHH + oidx] = (s7h > 0.f) ? 1.f : 0.f;
    }
}

// ---------------- launch ----------------
extern "C" void kernel_launch(void* const* d_in, const int* in_sizes, int n_in,
                              void* d_out, int out_size) {
    const float* tensor = (const float*)d_in[0];
    const float* mask   = (const float*)d_in[1];
    const float* weight = (const float*)d_in[2];
    const float* bias   = (const float*)d_in[3];
    const float* u      = (const float*)d_in[4];
    const float* beta   = (const float*)d_in[5];
    const float* gamma  = (const float*)d_in[6];
    float* out = (float*)d_out;

    cudaFuncSetAttribute(k_conv_mma, cudaFuncAttributeMaxDynamicSharedMemorySize, SMEM_MMA);
    cudaFuncSetAttribute(k_gdn_mma, cudaFuncAttributeMaxDynamicSharedMemorySize, SMEM_GDN);
    cudaFuncSetAttribute(k_dwt_fused, cudaFuncAttributeMaxDynamicSharedMemorySize, SMEM_DWT);
    cudaFuncSetAttribute(k_mask_fused, cudaFuncAttributeMaxDynamicSharedMemorySize, SMEM_MASK);

    k_sigma<<<1, 576>>>(weight, u);
    k_prepw<<<288, 256>>>();
    k_prepg<<<64, 256>>>(gamma);
    k_ratio<<<(NB*HWSZ)/256, 256>>>(mask);
    k_conv_mma<<<dim3(4, 128, NB), 256, SMEM_MMA>>>(tensor, mask, bias);
    k_gdn_mma<<<(NB*HWSZ)/128, 256, SMEM_GDN>>>(beta);
    k_dwt_fused<<<dim3(8, NB*CO), 256, SMEM_DWT>>>(out);
    k_mask_fused<<<dim3(8, NB), 256, SMEM_MASK>>>(out);
}

// round 15
// speedup vs baseline: 1.8513x; 1.1475x over previous
#include <cuda_runtime.h>
#include <cuda_bf16.h>
#include <math.h>
#include <stdint.h>

#define NB   8
#define CIN  64
#define CO   128
#define HH0  256
#define WW0  256
#define HWSZ 65536
#define HD   128
#define WD   128

// ---------------- scratch ----------------
__device__ float g_wsn[CO*CIN*9];
__device__ unsigned char g_wB[9*34816];     // per-tap [hi|lo][64 c-rows x 272B (128 o bf16 + pad)]
__device__ unsigned char g_gB2[98304];      // gamma chunks: [ks:8][hi|lo][128 o x 48B]
__device__ float g_ratio[NB*HWSZ];
__device__ float g_mvalid[NB*HWSZ];
__device__ float g_y[(size_t)NB*CO*HWSZ];

__constant__ float c_H0[9] = {
    0.026748757410810f, -0.016864118442875f, -0.078223266528990f,
    0.266864118442875f,  0.602949018236360f,  0.266864118442875f,
   -0.078223266528990f, -0.016864118442875f,  0.026748757410810f};
__constant__ float c_H1[7] = {
    0.091271763114250f, -0.057543526228500f, -0.591271763114250f,
    1.115087052457000f, -0.591271763114250f, -0.057543526228500f,
    0.091271763114250f};

#define SZ_BAND ((size_t)NB*CO*HD*WD)
#define SZ_MASK ((size_t)NB*HD*WD)
#define OFS_LL   ((size_t)0)
#define OFS_MLL  (OFS_LL  + SZ_BAND)
#define OFS_LH   (OFS_MLL + SZ_MASK)
#define OFS_HL   (OFS_LH  + SZ_BAND)
#define OFS_HH   (OFS_HL  + SZ_BAND)
#define OFS_MLH  (OFS_HH  + SZ_BAND)
#define OFS_MHL  (OFS_MLH + SZ_MASK)
#define OFS_MHH  (OFS_MHL + SZ_MASK)

__device__ __forceinline__ int refl(int j, int n) {
    if (j < 0) j = -j;
    if (j >= n) j = 2*n - 2 - j;
    return j;
}

// ---------------- mma.sync / ldmatrix / cp.async helpers (baseline PTX, sm_80+) ----------
__device__ __forceinline__ uint32_t smem_u32(const void* p) {
    uint32_t a;
    asm("{ .reg .u64 t; cvta.to.shared.u64 t, %1; cvt.u32.u64 %0, t; }" : "=r"(a) : "l"(p));
    return a;
}
__device__ __forceinline__ void ldsm4(uint32_t* r, uint32_t a) {
    asm volatile("ldmatrix.sync.aligned.m8n8.x4.shared.b16 {%0,%1,%2,%3}, [%4];"
        : "=r"(r[0]), "=r"(r[1]), "=r"(r[2]), "=r"(r[3]) : "r"(a));
}
__device__ __forceinline__ void ldsm4t(uint32_t* r, uint32_t a) {
    asm volatile("ldmatrix.sync.aligned.m8n8.x4.trans.shared.b16 {%0,%1,%2,%3}, [%4];"
        : "=r"(r[0]), "=r"(r[1]), "=r"(r[2]), "=r"(r[3]) : "r"(a));
}
__device__ __forceinline__ void mma16816(float* c, const uint32_t* a, const uint32_t* b) {
    asm volatile("mma.sync.aligned.m16n8k16.row.col.f32.bf16.bf16.f32 "
        "{%0,%1,%2,%3},{%4,%5,%6,%7},{%8,%9},{%0,%1,%2,%3};"
        : "+f"(c[0]), "+f"(c[1]), "+f"(c[2]), "+f"(c[3])
        : "r"(a[0]), "r"(a[1]), "r"(a[2]), "r"(a[3]), "r"(b[0]), "r"(b[1]));
}
__device__ __forceinline__ void cpa16(uint32_t s, const void* g) {
    asm volatile("cp.async.cg.shared.global [%0], [%1], 16;" :: "r"(s), "l"(g) : "memory");
}
__device__ __forceinline__ void cpa_commit() {
    asm volatile("cp.async.commit_group;" ::: "memory");
}
__device__ __forceinline__ void cpa_wait0() {
    asm volatile("cp.async.wait_group 0;" ::: "memory");
}

// ---------------- K0: spectral norm -> g_wsn ----------------
__global__ void k_sigma(const float* __restrict__ w, const float* __restrict__ u) {
    __shared__ float sv[576];
    __shared__ float red[576];
    __shared__ float s_bcast;
    int t = threadIdx.x;

    float vj = 0.f;
    for (int o = 0; o < CO; ++o) vj += w[o*576 + t] * u[o];
    red[t] = vj*vj;
    sv[t] = vj;
    __syncthreads();
    if (t == 0) {
        float s = 0.f;
        for (int i = 0; i < 576; ++i) s += red[i];
        s_bcast = 1.f / (sqrtf(s) + 1e-12f);
    }
    __syncthreads();
    float vn = sv[t] * s_bcast;
    __syncthreads();
    sv[t] = vn;
    __syncthreads();

    if (t < CO) {
        float s = 0.f;
        for (int j = 0; j < 576; ++j) s += w[t*576 + j] * sv[j];
        red[t] = s*s;
    }
    __syncthreads();
    if (t == 0) {
        float s = 0.f;
        for (int i = 0; i < CO; ++i) s += red[i];
        s_bcast = 1.f / sqrtf(s);
    }
    __syncthreads();
    float inv_sigma = s_bcast;
    for (int i = t; i < CO*CIN*9; i += 576) g_wsn[i] = w[i] * inv_sigma;
}

// ---------------- K0b: weights -> per-tap [c][o] bf16 hi/lo rows (272B stride) --------
__global__ void k_prepw() {
    int idx = blockIdx.x*256 + threadIdx.x;
    if (idx >= 9*CIN*CO) return;
    int q = idx >> 13;
    int rem = idx & 8191;
    int c = rem >> 7;
    int o = rem & 127;
    float v = g_wsn[(o*CIN + c)*9 + q];
    __nv_bfloat16 hi = __float2bfloat16(v);
    __nv_bfloat16 lo = __float2bfloat16(v - __bfloat162float(hi));
    size_t base = (size_t)q*34816;
    *(__nv_bfloat16*)(g_wB + base +         c*272 + o*2) = hi;
    *(__nv_bfloat16*)(g_wB + base + 17408 + c*272 + o*2) = lo;
}

// ---------------- K0c: gamma -> 8 chunks [hi|lo][128 o][48B] (16 c per chunk) --------
__global__ void k_prepg(const float* __restrict__ gamma) {
    int idx = blockIdx.x*256 + threadIdx.x;   // 16384 = 8ks * 128o * 16k
    if (idx >= 8*128*16) return;
    int ks = idx >> 11;
    int o  = (idx >> 4) & 127;
    int k  = idx & 15;
    float v = gamma[o*CO + ks*16 + k];
    __nv_bfloat16 hi = __float2bfloat16(v);
    __nv_bfloat16 lo = __float2bfloat16(v - __bfloat162float(hi));
    *(__nv_bfloat16*)(g_gB2 + ks*12288 +        o*48 + k*2) = hi;
    *(__nv_bfloat16*)(g_gB2 + ks*12288 + 6144 + o*48 + k*2) = lo;
}

// ---------------- K1: mask 3x3 box -> ratio + valid ----------------
__global__ void k_ratio(const float* __restrict__ mask) {
    int idx = blockIdx.x*256 + threadIdx.x;
    int b = idx >> 16;
    int hw = idx & 65535;
    int h = hw >> 8, wx = hw & 255;
    const float* mb = mask + (size_t)b*HWSZ;
    float s = 0.f;
    #pragma unroll
    for (int dh = -1; dh <= 1; ++dh) {
        int h2 = h + dh;
        if (h2 < 0 || h2 >= HH0) continue;
        #pragma unroll
        for (int dw = -1; dw <= 1; ++dw) {
            int w2 = wx + dw;
            if (w2 < 0 || w2 >= WW0) continue;
            s += mb[h2*WW0 + w2];
        }
    }
    bool valid = s > 0.f;
    g_mvalid[idx] = valid ? 1.f : 0.f;
    g_ratio[idx]  = valid ? 9.f / fmaxf(s, 1e-8f) : 0.f;
}

// ---------------- K2: mma.sync implicit-GEMM conv (bf16 3-term split) ----------------
// Single-buffered weights -> smem 110848 -> 2 CTAs/SM. D stride 132 (float4 epilogue).
#define P_HI 0
#define P_LO 38016
#define BW0  76032
#define SMEM_MMA 110848

extern __shared__ char smc[];

__global__ void __launch_bounds__(256, 2) k_conv_mma(const float* __restrict__ x,
                                                     const float* __restrict__ mask,
                                                     const float* __restrict__ bias) {
    uint32_t sb = smem_u32(smc);
    int t = threadIdx.x, l = t & 31, wid = t >> 5;
    int w0 = blockIdx.x * 64, h0 = blockIdx.y * 2, b = blockIdx.z;
    int warp_m = wid & 1;
    int warp_n = wid >> 1;

    // prefetch tap 0
    for (int i = t; i < 2176; i += 256)
        cpa16(sb + BW0 + i*16, g_wB + i*16);
    cpa_commit();

    // patch fill: 64c x 4rows x 66w of (x*mask), bf16 hi/lo
    for (int i = t; i < 16896; i += 256) {
        int w = i % 66;
        int rem = i / 66;
        int r = rem & 3;
        int c = rem >> 2;
        int h = h0 - 1 + r, wx = w0 - 1 + w;
        float v = 0.f;
        if (h >= 0 && h < HH0 && wx >= 0 && wx < WW0)
            v = x[(((size_t)b*CIN + c)*HH0 + h)*WW0 + wx]
              * mask[((size_t)b*HH0 + h)*WW0 + wx];
        __nv_bfloat16 hi = __float2bfloat16(v);
        __nv_bfloat16 lo = __float2bfloat16(v - __bfloat162float(hi));
        int off = (r*66 + w)*144 + c*2;
        *(__nv_bfloat16*)(smc + P_HI + off) = hi;
        *(__nv_bfloat16*)(smc + P_LO + off) = lo;
    }
    cpa_wait0();
    __syncthreads();

    float acc[4][4][4];
    #pragma unroll
    for (int mi = 0; mi < 4; ++mi)
        #pragma unroll
        for (int ni = 0; ni < 4; ++ni)
            #pragma unroll
            for (int k = 0; k < 4; ++k) acc[mi][ni][k] = 0.f;

    int lane15 = l & 15;
    int kh8 = ((l >> 4) & 1) * 8;
    int noff = ((l >> 4) & 1) * 8;

    for (int q = 0; q < 9; ++q) {
        int kh = q / 3, kw = q - kh*3;
        uint32_t bwbase = sb + BW0;
        int prow0 = ((warp_m + kh)*66 + kw) * 144;

        #pragma unroll
        for (int ks = 0; ks < 4; ++ks) {
            int k0 = ks * 16;
            uint32_t aH[4][4], aL[4][4];
            #pragma unroll
            for (int mi = 0; mi < 4; ++mi) {
                uint32_t off = (uint32_t)(prow0 + (mi*16 + lane15)*144 + (k0 + kh8)*2);
                ldsm4(aH[mi], sb + P_HI + off);
                ldsm4(aL[mi], sb + P_LO + off);
            }
            uint32_t bH[2][4], bL[2][4];
            #pragma unroll
            for (int n2 = 0; n2 < 2; ++n2) {
                uint32_t boff = (uint32_t)((k0 + lane15)*272 + (warp_n*32 + n2*16 + noff)*2);
                ldsm4t(bH[n2], bwbase + boff);
                ldsm4t(bL[n2], bwbase + 17408 + boff);
            }
            #pragma unroll
            for (int mi = 0; mi < 4; ++mi)
                #pragma unroll
                for (int ni = 0; ni < 4; ++ni) {
                    const uint32_t* bh = &bH[ni >> 1][(ni & 1)*2];
                    const uint32_t* bl = &bL[ni >> 1][(ni & 1)*2];
                    mma16816(acc[mi][ni], aH[mi], bh);
                    mma16816(acc[mi][ni], aH[mi], bl);
                    mma16816(acc[mi][ni], aL[mi], bh);
                }
        }

        __syncthreads();    // all warps done reading BW0 before overwrite
        if (q < 8) {
            const unsigned char* src = g_wB + (size_t)(q + 1)*34816;
            for (int i = t; i < 2176; i += 256)
                cpa16(sb + BW0 + i*16, src + i*16);
            cpa_commit();
            cpa_wait0();
            __syncthreads();
        }
    }

    __syncthreads();
    float* D = (float*)smc;     // [o:128][132]
    #pragma unroll
    for (int mi = 0; mi < 4; ++mi)
        #pragma unroll
        for (int ni = 0; ni < 4; ++ni) {
            int px = warp_m*64 + mi*16 + (l >> 2);
            int o  = warp_n*32 + ni*8 + 2*(l & 3);
            D[o*132 + px]           = acc[mi][ni][0];
            D[(o + 1)*132 + px]     = acc[mi][ni][1];
            D[o*132 + px + 8]       = acc[mi][ni][2];
            D[(o + 1)*132 + px + 8] = acc[mi][ni][3];
        }
    __syncthreads();

    // vectorized epilogue: float4 D reads, float4 g_y writes
    int w4 = (t & 15) * 4;
    int ob = t >> 4;               // 0..15
    #pragma unroll
    for (int r = 0; r < 2; ++r) {
        int h = h0 + r;
        float4 rt4 = *(const float4*)&g_ratio[((size_t)b*HH0 + h)*WW0 + w0 + w4];
        #pragma unroll
        for (int oo = 0; oo < 8; ++oo) {
            int o = ob + oo*16;
            float bv = bias[o];
            float4 v = *(const float4*)&D[o*132 + r*64 + w4];
            float4 outv;
            outv.x = (rt4.x > 0.f) ? v.x*rt4.x + bv : 0.f;
            outv.y = (rt4.y > 0.f) ? v.y*rt4.y + bv : 0.f;
            outv.z = (rt4.z > 0.f) ? v.z*rt4.z + bv : 0.f;
            outv.w = (rt4.w > 0.f) ? v.w*rt4.w + bv : 0.f;
            *(float4*)&g_y[(((size_t)b*CO + o)*HH0 + h)*WW0 + w0 + w4] = outv;
        }
    }
}

// ---------------- K3: GDN via mma.sync, chunked gamma -> 2 CTAs/SM ----------------
// M = 128 o (gamma chunks, ldsm4, 48B rows), N = 128 px (z = y^2, ldsm4t, 272B rows),
// K = 128 c in 8 chunks of 16. gamma double-buffered via cp.async. In-place on g_y.
#define GZ_HI  0
#define GZ_LO  34816
#define GB_OFS 69632          // 2 x 12288 gamma chunk buffers
#define SMEM_GDN 94208
#define S_OFS  0              // s[o:128][132] f32 overlays z after mma

__global__ void __launch_bounds__(256, 2) k_gdn_mma(const float* __restrict__ beta) {
    uint32_t sb = smem_u32(smc);
    int t = threadIdx.x, l = t & 31, wid = t >> 5;
    int warp_m = wid & 1;          // o half (64 each)
    int warp_n = wid >> 1;         // px quarter (32 each)

    size_t p0 = (size_t)blockIdx.x * 128;
    int b   = (int)(p0 >> 16);
    int hw0 = (int)(p0 & 65535);
    float* yb = g_y + (size_t)b*CO*HWSZ + hw0;

    // prefetch gamma chunk 0
    for (int i = t; i < 768; i += 256)
        cpa16(sb + GB_OFS + i*16, g_gB2 + i*16);
    cpa_commit();

    // stage z = y^2 as [c rows][128 px] bf16 hi/lo, 272B stride (float4 reads)
    for (int i = t; i < 4096; i += 256) {
        int c = i >> 5, p4 = (i & 31) * 4;
        float4 v = *(const float4*)&yb[(size_t)c*HWSZ + p4];
        float z0 = v.x*v.x, z1 = v.y*v.y, z2 = v.z*v.z, z3 = v.w*v.w;
        __nv_bfloat162 hp0, hp1, lp0, lp1;
        hp0.x = __float2bfloat16(z0); hp0.y = __float2bfloat16(z1);
        hp1.x = __float2bfloat16(z2); hp1.y = __float2bfloat16(z3);
        lp0.x = __float2bfloat16(z0 - __bfloat162float(hp0.x));
        lp0.y = __float2bfloat16(z1 - __bfloat162float(hp0.y));
        lp1.x = __float2bfloat16(z2 - __bfloat162float(hp1.x));
        lp1.y = __float2bfloat16(z3 - __bfloat162float(hp1.y));
        int off = c*272 + p4*2;
        *(__nv_bfloat162*)(smc + GZ_HI + off)     = hp0;
        *(__nv_bfloat162*)(smc + GZ_HI + off + 4) = hp1;
        *(__nv_bfloat162*)(smc + GZ_LO + off)     = lp0;
        *(__nv_bfloat162*)(smc + GZ_LO + off + 4) = lp1;
    }
    cpa_wait0();
    __syncthreads();

    float sacc[4][4][4];
    #pragma unroll
    for (int mi = 0; mi < 4; ++mi)
        #pragma unroll
        for (int ni = 0; ni < 4; ++ni)
            #pragma unroll
            for (int k = 0; k < 4; ++k) sacc[mi][ni][k] = 0.f;

    int lane15 = l & 15;
    int kh8 = ((l >> 4) & 1) * 8;
    int noff = ((l >> 4) & 1) * 8;

    for (int ks = 0; ks < 8; ++ks) {
        // prefetch next gamma chunk into the other buffer
        if (ks < 7) {
            uint32_t dst = sb + GB_OFS + ((ks + 1) & 1)*12288;
            const unsigned char* src = g_gB2 + (ks + 1)*12288;
            for (int i = t; i < 768; i += 256)
                cpa16(dst + i*16, src + i*16);
        }
        cpa_commit();

        int k0 = ks * 16;
        uint32_t gbuf = sb + GB_OFS + (ks & 1)*12288;
        uint32_t aH[4][4], aL[4][4];
        #pragma unroll
        for (int mi = 0; mi < 4; ++mi) {
            uint32_t off = (uint32_t)((warp_m*64 + mi*16 + lane15)*48 + kh8*2);
            ldsm4(aH[mi], gbuf + off);
            ldsm4(aL[mi], gbuf + 6144 + off);
        }
        uint32_t bH[2][4], bL[2][4];
        #pragma unroll
        for (int n2 = 0; n2 < 2; ++n2) {
            uint32_t boff = (uint32_t)((k0 + lane15)*272 + (warp_n*32 + n2*16 + noff)*2);
            ldsm4t(bH[n2], sb + GZ_HI + boff);
            ldsm4t(bL[n2], sb + GZ_LO + boff);
        }
        #pragma unroll
        for (int mi = 0; mi < 4; ++mi)
            #pragma unroll
            for (int ni = 0; ni < 4; ++ni) {
                const uint32_t* bh = &bH[ni >> 1][(ni & 1)*2];
                const uint32_t* bl = &bL[ni >> 1][(ni & 1)*2];
                mma16816(sacc[mi][ni], aH[mi], bh);
                mma16816(sacc[mi][ni], aH[mi], bl);
                mma16816(sacc[mi][ni], aL[mi], bh);
            }

        cpa_wait0();
        __syncthreads();
    }

    // s frags -> S[o][132] (overlays z)
    float* S = (float*)(smc + S_OFS);
    #pragma unroll
    for (int mi = 0; mi < 4; ++mi)
        #pragma unroll
        for (int ni = 0; ni < 4; ++ni) {
            int o  = warp_m*64 + mi*16 + (l >> 2);
            int px = warp_n*32 + ni*8 + 2*(l & 3);
            S[o*132 + px]           = sacc[mi][ni][0];
            S[o*132 + px + 1]       = sacc[mi][ni][1];
            S[(o + 8)*132 + px]     = sacc[mi][ni][2];
            S[(o + 8)*132 + px + 1] = sacc[mi][ni][3];
        }
    __syncthreads();

    // final: y = y * rsqrt(beta + s) * mask, float4 everywhere
    int px4 = (t & 31) * 4;
    int ob = t >> 5;               // 0..7
    float4 mv4 = *(const float4*)&g_mvalid[p0 + px4];
    #pragma unroll
    for (int oo = 0; oo < 16; ++oo) {
        int o = ob + oo*8;
        float bo = beta[o];
        float4 s4 = *(const float4*)&S[o*132 + px4];
        size_t ad = (size_t)o*HWSZ + px4;
        float4 xv = *(const float4*)&yb[ad];
        float4 r;
        r.x = xv.x * rsqrtf(bo + s4.x) * mv4.x;
        r.y = xv.y * rsqrtf(bo + s4.y) * mv4.y;
        r.z = xv.z * rsqrtf(bo + s4.z) * mv4.z;
        r.w = xv.w * rsqrtf(bo + s4.w) * mv4.w;
        *(float4*)&yb[ad] = r;
    }
}

// ---------------- K4: fused DWT (rows + cols in one pass) -> 4 bands ----------------
#define DX_OFS 0          // xs[39][256] floats
#define DL_OFS 9984       // lo[16][260]
#define DH_OFS 14144      // hi[16][260]
#define SMEM_DWT 73216    // 18304 floats

__global__ void __launch_bounds__(256) k_dwt_fused(float* __restrict__ out) {
    float* sm = (float*)smc;
    float* xs = sm + DX_OFS;
    float* lo = sm + DL_OFS;
    float* hi = sm + DH_OFS;

    int t = threadIdx.x;
    int hr0 = blockIdx.x * 16;
    int bc  = blockIdx.y;
    const float* img = g_y + (size_t)bc*HWSZ;

    for (int i = t; i < 9984; i += 256) {
        int r = i >> 8, w = i & 255;
        int h = refl(2*hr0 - 4 + r, HH0);
        xs[r*256 + w] = img[h*WW0 + w];
    }
    __syncthreads();

    {
        int w = t;
        #pragma unroll 4
        for (int d = 0; d < 16; ++d) {
            const float* col = xs + 2*d*256 + w;
            float a0 = col[0],      a1 = col[256],  a2 = col[512],  a3 = col[768];
            float a4 = col[1024],   a5 = col[1280], a6 = col[1536], a7 = col[1792];
            float a8 = col[2048];
            float lv = c_H0[0]*a0 + c_H0[1]*a1 + c_H0[2]*a2 + c_H0[3]*a3 + c_H0[4]*a4
                     + c_H0[5]*a5 + c_H0[6]*a6 + c_H0[7]*a7 + c_H0[8]*a8;
            float hv = c_H1[0]*a1 + c_H1[1]*a2 + c_H1[2]*a3 + c_H1[3]*a4
                     + c_H1[4]*a5 + c_H1[5]*a6 + c_H1[6]*a7;
            lo[d*260 + w] = lv;
            hi[d*260 + w] = hv;
        }
    }
    __syncthreads();

    size_t obase = (size_t)bc*HD*WD;
    for (int i = t; i < 2048; i += 256) {
        int wr = i & 127, d = i >> 7;
        const float* lrow = lo + d*260;
        const float* hrow = hi + d*260;
        float rl[9], rh[9];
        #pragma unroll
        for (int k = 0; k < 9; ++k) {
            int j = refl(2*wr + k - 4, WW0);
            rl[k] = lrow[j];
            rh[k] = hrow[j];
        }
        float ll = 0.f, lh = 0.f, hl = 0.f, hh = 0.f;
        #pragma unroll
        for (int k = 0; k < 9; ++k) { ll += c_H0[k]*rl[k]; hl += c_H0[k]*rh[k]; }
        #pragma unroll
        for (int k = 0; k < 7; ++k) { lh += c_H1[k]*rl[k+1]; hh += c_H1[k]*rh[k+1]; }
        size_t oidx = obase + (size_t)(hr0 + d)*WD + wr;
        out[OFS_LL + oidx] = ll;
        out[OFS_LH + oidx] = lh;
        out[OFS_HL + oidx] = hl;
        out[OFS_HH + oidx] = hh;
    }
}

// ---------------- K5: fused mask downsample (H + W in one pass) -> 4 mask bands ------
#define MK_X   0
#define MK_LO  9984
#define MK_HI  14080
#define SMEM_MASK 72704

__global__ void __launch_bounds__(256) k_mask_fused(float* __restrict__ out) {
    float* sm  = (float*)smc;
    float* ms  = sm + MK_X;     // [39][256]
    float* mlo = sm + MK_LO;    // [16][256]
    float* mhi = sm + MK_HI;    // [16][256]

    int t = threadIdx.x;
    int hr0 = blockIdx.x * 16;
    int b   = blockIdx.y;
    const float* mv = g_mvalid + (size_t)b*HWSZ;

    for (int i = t; i < 9984; i += 256) {
        int r = i >> 8, w = i & 255;
        int h = refl(2*hr0 - 4 + r, HH0);
        ms[r*256 + w] = mv[h*WW0 + w];
    }
    __syncthreads();

    {
        int w = t;
        #pragma unroll 4
        for (int d = 0; d < 16; ++d) {
            const float* col = ms + 2*d*256 + w;
            float s9 = 0.f, s7 = 0.f;
            #pragma unroll
            for (int k = 0; k < 9; ++k) {
                float v = col[k*256];
                s9 += v;
                if (k >= 1 && k <= 7) s7 += v;
            }
            mlo[d*256 + w] = (s9 > 0.f) ? 1.f : 0.f;
            mhi[d*256 + w] = (s7 > 0.f) ? 1.f : 0.f;
        }
    }
    __syncthreads();

    size_t obase = (size_t)b*HD*WD;
    for (int i = t; i < 2048; i += 256) {
        int wr = i & 127, d = i >> 7;
        const float* lrow = mlo + d*256;
        const float* hrow = mhi + d*256;
        float s9l = 0.f, s7l = 0.f, s9h = 0.f, s7h = 0.f;
        #pragma unroll
        for (int k = 0; k < 9; ++k) {
            int j = refl(2*wr + k - 4, WW0);
            float vl = lrow[j], vh = hrow[j];
            s9l += vl; s9h += vh;
            if (k >= 1 && k <= 7) { s7l += vl; s7h += vh; }
        }
        size_t oidx = obase + (size_t)(hr0 + d)*WD + wr;
        out[OFS_MLL + oidx] = (s9l > 0.f) ? 1.f : 0.f;
        out[OFS_MLH + oidx] = (s7l > 0.f) ? 1.f : 0.f;
        out[OFS_MHL + oidx] = (s9h > 0.f) ? 1.f : 0.f;
        out[OFS_MHH + oidx] = (s7h > 0.f) ? 1.f : 0.f;
    }
}

// ---------------- launch ----------------
extern "C" void kernel_launch(void* const* d_in, const int* in_sizes, int n_in,
                              void* d_out, int out_size) {
    const float* tensor = (const float*)d_in[0];
    const float* mask   = (const float*)d_in[1];
    const float* weight = (const float*)d_in[2];
    const float* bias   = (const float*)d_in[3];
    const float* u      = (const float*)d_in[4];
    const float* beta   = (const float*)d_in[5];
    const float* gamma  = (const float*)d_in[6];
    float* out = (float*)d_out;

    cudaFuncSetAttribute(k_conv_mma, cudaFuncAttributeMaxDynamicSharedMemorySize, SMEM_MMA);
    cudaFuncSetAttribute(k_gdn_mma, cudaFuncAttributeMaxDynamicSharedMemorySize, SMEM_GDN);
    cudaFuncSetAttribute(k_dwt_fused, cudaFuncAttributeMaxDynamicSharedMemorySize, SMEM_DWT);
    cudaFuncSetAttribute(k_mask_fused, cudaFuncAttributeMaxDynamicSharedMemorySize, SMEM_MASK);

    k_sigma<<<1, 576>>>(weight, u);
    k_prepw<<<288, 256>>>();
    k_prepg<<<64, 256>>>(gamma);
    k_ratio<<<(NB*HWSZ)/256, 256>>>(mask);
    k_conv_mma<<<dim3(4, 128, NB), 256, SMEM_MMA>>>(tensor, mask, bias);
    k_gdn_mma<<<(NB*HWSZ)/128, 256, SMEM_GDN>>>(beta);
    k_dwt_fused<<<dim3(8, NB*CO), 256, SMEM_DWT>>>(out);
    k_mask_fused<<<dim3(8, NB), 256, SMEM_MASK>>>(out);
}

// round 16
// speedup vs baseline: 2.0498x; 1.1072x over previous
#include <cuda_runtime.h>
#include <cuda_bf16.h>
#include <math.h>
#include <stdint.h>

#define NB   8
#define CIN  64
#define CO   128
#define HH0  256
#define WW0  256
#define HWSZ 65536
#define HD   128
#define WD   128

// ---------------- scratch ----------------
__device__ float g_wsn[CO*CIN*9];
__device__ unsigned char g_wB[9*34816];     // [q][half:2][hi|lo][32 c-rows x 272B]
__device__ unsigned char g_gB2[98304];      // gamma chunks: [ks:8][hi|lo][128 o x 48B]
__device__ float g_ratio[NB*HWSZ];
__device__ float g_mvalid[NB*HWSZ];
__device__ float g_y[(size_t)NB*CO*HWSZ];

__constant__ float c_H0[9] = {
    0.026748757410810f, -0.016864118442875f, -0.078223266528990f,
    0.266864118442875f,  0.602949018236360f,  0.266864118442875f,
   -0.078223266528990f, -0.016864118442875f,  0.026748757410810f};
__constant__ float c_H1[7] = {
    0.091271763114250f, -0.057543526228500f, -0.591271763114250f,
    1.115087052457000f, -0.591271763114250f, -0.057543526228500f,
    0.091271763114250f};

#define SZ_BAND ((size_t)NB*CO*HD*WD)
#define SZ_MASK ((size_t)NB*HD*WD)
#define OFS_LL   ((size_t)0)
#define OFS_MLL  (OFS_LL  + SZ_BAND)
#define OFS_LH   (OFS_MLL + SZ_MASK)
#define OFS_HL   (OFS_LH  + SZ_BAND)
#define OFS_HH   (OFS_HL  + SZ_BAND)
#define OFS_MLH  (OFS_HH  + SZ_BAND)
#define OFS_MHL  (OFS_MLH + SZ_MASK)
#define OFS_MHH  (OFS_MHL + SZ_MASK)

__device__ __forceinline__ int refl(int j, int n) {
    if (j < 0) j = -j;
    if (j >= n) j = 2*n - 2 - j;
    return j;
}

// ---------------- mma.sync / ldmatrix / cp.async helpers (baseline PTX, sm_80+) ----------
__device__ __forceinline__ uint32_t smem_u32(const void* p) {
    uint32_t a;
    asm("{ .reg .u64 t; cvta.to.shared.u64 t, %1; cvt.u32.u64 %0, t; }" : "=r"(a) : "l"(p));
    return a;
}
__device__ __forceinline__ void ldsm4(uint32_t* r, uint32_t a) {
    asm volatile("ldmatrix.sync.aligned.m8n8.x4.shared.b16 {%0,%1,%2,%3}, [%4];"
        : "=r"(r[0]), "=r"(r[1]), "=r"(r[2]), "=r"(r[3]) : "r"(a));
}
__device__ __forceinline__ void ldsm4t(uint32_t* r, uint32_t a) {
    asm volatile("ldmatrix.sync.aligned.m8n8.x4.trans.shared.b16 {%0,%1,%2,%3}, [%4];"
        : "=r"(r[0]), "=r"(r[1]), "=r"(r[2]), "=r"(r[3]) : "r"(a));
}
__device__ __forceinline__ void mma16816(float* c, const uint32_t* a, const uint32_t* b) {
    asm volatile("mma.sync.aligned.m16n8k16.row.col.f32.bf16.bf16.f32 "
        "{%0,%1,%2,%3},{%4,%5,%6,%7},{%8,%9},{%0,%1,%2,%3};"
        : "+f"(c[0]), "+f"(c[1]), "+f"(c[2]), "+f"(c[3])
        : "r"(a[0]), "r"(a[1]), "r"(a[2]), "r"(a[3]), "r"(b[0]), "r"(b[1]));
}
__device__ __forceinline__ void cpa16(uint32_t s, const void* g) {
    asm volatile("cp.async.cg.shared.global [%0], [%1], 16;" :: "r"(s), "l"(g) : "memory");
}
__device__ __forceinline__ void cpa_commit() {
    asm volatile("cp.async.commit_group;" ::: "memory");
}
__device__ __forceinline__ void cpa_wait1() {
    asm volatile("cp.async.wait_group 1;" ::: "memory");
}
__device__ __forceinline__ void cpa_wait0() {
    asm volatile("cp.async.wait_group 0;" ::: "memory");
}

// ---------------- K0: spectral norm -> g_wsn ----------------
__global__ void k_sigma(const float* __restrict__ w, const float* __restrict__ u) {
    __shared__ float sv[576];
    __shared__ float red[576];
    __shared__ float s_bcast;
    int t = threadIdx.x;

    float vj = 0.f;
    for (int o = 0; o < CO; ++o) vj += w[o*576 + t] * u[o];
    red[t] = vj*vj;
    sv[t] = vj;
    __syncthreads();
    if (t == 0) {
        float s = 0.f;
        for (int i = 0; i < 576; ++i) s += red[i];
        s_bcast = 1.f / (sqrtf(s) + 1e-12f);
    }
    __syncthreads();
    float vn = sv[t] * s_bcast;
    __syncthreads();
    sv[t] = vn;
    __syncthreads();

    if (t < CO) {
        float s = 0.f;
        for (int j = 0; j < 576; ++j) s += w[t*576 + j] * sv[j];
        red[t] = s*s;
    }
    __syncthreads();
    if (t == 0) {
        float s = 0.f;
        for (int i = 0; i < CO; ++i) s += red[i];
        s_bcast = 1.f / sqrtf(s);
    }
    __syncthreads();
    float inv_sigma = s_bcast;
    for (int i = t; i < CO*CIN*9; i += 576) g_wsn[i] = w[i] * inv_sigma;
}

// ---------------- K0b: weights -> [q][half][hi|lo][32 c-rows x 272B] ----------------
__global__ void k_prepw() {
    int idx = blockIdx.x*256 + threadIdx.x;
    if (idx >= 9*CIN*CO) return;
    int q = idx >> 13;
    int rem = idx & 8191;
    int c = rem >> 7;
    int o = rem & 127;
    float v = g_wsn[(o*CIN + c)*9 + q];
    __nv_bfloat16 hi = __float2bfloat16(v);
    __nv_bfloat16 lo = __float2bfloat16(v - __bfloat162float(hi));
    int half = c >> 5, cl = c & 31;
    size_t base = (size_t)q*34816 + (size_t)half*17408;
    *(__nv_bfloat16*)(g_wB + base +        cl*272 + o*2) = hi;
    *(__nv_bfloat16*)(g_wB + base + 8704 + cl*272 + o*2) = lo;
}

// ---------------- K0c: gamma -> 8 chunks [hi|lo][128 o][48B] (16 c per chunk) --------
__global__ void k_prepg(const float* __restrict__ gamma) {
    int idx = blockIdx.x*256 + threadIdx.x;   // 16384 = 8ks * 128o * 16k
    if (idx >= 8*128*16) return;
    int ks = idx >> 11;
    int o  = (idx >> 4) & 127;
    int k  = idx & 15;
    float v = gamma[o*CO + ks*16 + k];
    __nv_bfloat16 hi = __float2bfloat16(v);
    __nv_bfloat16 lo = __float2bfloat16(v - __bfloat162float(hi));
    *(__nv_bfloat16*)(g_gB2 + ks*12288 +        o*48 + k*2) = hi;
    *(__nv_bfloat16*)(g_gB2 + ks*12288 + 6144 + o*48 + k*2) = lo;
}

// ---------------- K1: mask 3x3 box -> ratio + valid ----------------
__global__ void k_ratio(const float* __restrict__ mask) {
    int idx = blockIdx.x*256 + threadIdx.x;
    int b = idx >> 16;
    int hw = idx & 65535;
    int h = hw >> 8, wx = hw & 255;
    const float* mb = mask + (size_t)b*HWSZ;
    float s = 0.f;
    #pragma unroll
    for (int dh = -1; dh <= 1; ++dh) {
        int h2 = h + dh;
        if (h2 < 0 || h2 >= HH0) continue;
        #pragma unroll
        for (int dw = -1; dw <= 1; ++dw) {
            int w2 = wx + dw;
            if (w2 < 0 || w2 >= WW0) continue;
            s += mb[h2*WW0 + w2];
        }
    }
    bool valid = s > 0.f;
    g_mvalid[idx] = valid ? 1.f : 0.f;
    g_ratio[idx]  = valid ? 9.f / fmaxf(s, 1e-8f) : 0.f;
}

// ---------------- K2: mma.sync implicit-GEMM conv (bf16 3-term split) ----------------
// Half-tap pipelined weights: two 17408B buffers in the same 34816B footprint;
// load of half s+2 overlaps MMA of half s. smem 110848 -> 2 CTAs/SM.
#define P_HI 0
#define P_LO 38016
#define BWA  76032
#define BWB  93440
#define SMEM_MMA 110848

extern __shared__ char smc[];

__global__ void __launch_bounds__(256, 2) k_conv_mma(const float* __restrict__ x,
                                                     const float* __restrict__ mask,
                                                     const float* __restrict__ bias) {
    uint32_t sb = smem_u32(smc);
    int t = threadIdx.x, l = t & 31, wid = t >> 5;
    int w0 = blockIdx.x * 64, h0 = blockIdx.y * 2, b = blockIdx.z;
    int warp_m = wid & 1;
    int warp_n = wid >> 1;

    // prologue: prefetch half-steps 0, 1 (tap 0 halves) as two groups
    for (int i = t; i < 1088; i += 256)
        cpa16(sb + BWA + i*16, g_wB + i*16);
    cpa_commit();
    for (int i = t; i < 1088; i += 256)
        cpa16(sb + BWB + i*16, g_wB + 17408 + i*16);
    cpa_commit();

    // patch fill: thread owns fixed (r,w), loads mask once, loops c (coalesced x reads)
    for (int rw = t; rw < 264; rw += 256) {
        int r = rw / 66, w = rw - r*66;
        int h = h0 - 1 + r, wx = w0 - 1 + w;
        bool inb = (h >= 0 && h < HH0 && wx >= 0 && wx < WW0);
        float mv = 0.f;
        const float* xp = x;
        if (inb) {
            mv = mask[(size_t)b*HWSZ + h*WW0 + wx];
            xp = x + (size_t)b*CIN*HWSZ + h*WW0 + wx;
        }
        int off0 = (r*66 + w)*144;
        #pragma unroll 8
        for (int c = 0; c < CIN; ++c) {
            float v = inb ? xp[(size_t)c*HWSZ] * mv : 0.f;
            __nv_bfloat16 hi = __float2bfloat16(v);
            __nv_bfloat16 lo = __float2bfloat16(v - __bfloat162float(hi));
            *(__nv_bfloat16*)(smc + P_HI + off0 + c*2) = hi;
            *(__nv_bfloat16*)(smc + P_LO + off0 + c*2) = lo;
        }
    }

    float acc[4][4][4];
    #pragma unroll
    for (int mi = 0; mi < 4; ++mi)
        #pragma unroll
        for (int ni = 0; ni < 4; ++ni)
            #pragma unroll
            for (int k = 0; k < 4; ++k) acc[mi][ni][k] = 0.f;

    int lane15 = l & 15;
    int kh8 = ((l >> 4) & 1) * 8;
    int noff = ((l >> 4) & 1) * 8;

    // 18 half-steps: s -> tap q = s>>1, c-half = s&1 (ks pairs {0,1} / {2,3})
    for (int s = 0; s < 18; ++s) {
        int q = s >> 1;
        int kh = q / 3, kw = q - kh*3;
        uint32_t bwbase = sb + ((s & 1) ? BWB : BWA);
        int prow0 = ((warp_m + kh)*66 + kw) * 144;

        if (s < 17) cpa_wait1(); else cpa_wait0();
        __syncthreads();

        #pragma unroll
        for (int kk = 0; kk < 2; ++kk) {
            int ks = (s & 1)*2 + kk;
            int k0 = ks * 16;
            int k0h = k0 & 31;            // c offset within the half buffer
            uint32_t aH[4][4], aL[4][4];
            #pragma unroll
            for (int mi = 0; mi < 4; ++mi) {
                uint32_t off = (uint32_t)(prow0 + (mi*16 + lane15)*144 + (k0 + kh8)*2);
                ldsm4(aH[mi], sb + P_HI + off);
                ldsm4(aL[mi], sb + P_LO + off);
            }
            uint32_t bH[2][4], bL[2][4];
            #pragma unroll
            for (int n2 = 0; n2 < 2; ++n2) {
                uint32_t boff = (uint32_t)((k0h + lane15)*272 + (warp_n*32 + n2*16 + noff)*2);
                ldsm4t(bH[n2], bwbase + boff);
                ldsm4t(bL[n2], bwbase + 8704 + boff);
            }
            #pragma unroll
            for (int mi = 0; mi < 4; ++mi)
                #pragma unroll
                for (int ni = 0; ni < 4; ++ni) {
                    const uint32_t* bh = &bH[ni >> 1][(ni & 1)*2];
                    const uint32_t* bl = &bL[ni >> 1][(ni & 1)*2];
                    mma16816(acc[mi][ni], aH[mi], bh);
                    mma16816(acc[mi][ni], aH[mi], bl);
                    mma16816(acc[mi][ni], aL[mi], bh);
                }
        }

        __syncthreads();    // all warps done reading this buffer before overwrite
        if (s < 16) {
            uint32_t dst = sb + ((s & 1) ? BWB : BWA);
            const unsigned char* src = g_wB + (size_t)(s + 2)*17408;
            for (int i = t; i < 1088; i += 256)
                cpa16(dst + i*16, src + i*16);
            cpa_commit();
        }
    }

    __syncthreads();
    float* D = (float*)smc;     // [o:128][132]
    #pragma unroll
    for (int mi = 0; mi < 4; ++mi)
        #pragma unroll
        for (int ni = 0; ni < 4; ++ni) {
            int px = warp_m*64 + mi*16 + (l >> 2);
            int o  = warp_n*32 + ni*8 + 2*(l & 3);
            D[o*132 + px]           = acc[mi][ni][0];
            D[(o + 1)*132 + px]     = acc[mi][ni][1];
            D[o*132 + px + 8]       = acc[mi][ni][2];
            D[(o + 1)*132 + px + 8] = acc[mi][ni][3];
        }
    __syncthreads();

    // vectorized epilogue: float4 D reads, float4 g_y writes
    int w4 = (t & 15) * 4;
    int ob = t >> 4;               // 0..15
    #pragma unroll
    for (int r = 0; r < 2; ++r) {
        int h = h0 + r;
        float4 rt4 = *(const float4*)&g_ratio[((size_t)b*HH0 + h)*WW0 + w0 + w4];
        #pragma unroll
        for (int oo = 0; oo < 8; ++oo) {
            int o = ob + oo*16;
            float bv = bias[o];
            float4 v = *(const float4*)&D[o*132 + r*64 + w4];
            float4 outv;
            outv.x = (rt4.x > 0.f) ? v.x*rt4.x + bv : 0.f;
            outv.y = (rt4.y > 0.f) ? v.y*rt4.y + bv : 0.f;
            outv.z = (rt4.z > 0.f) ? v.z*rt4.z + bv : 0.f;
            outv.w = (rt4.w > 0.f) ? v.w*rt4.w + bv : 0.f;
            *(float4*)&g_y[(((size_t)b*CO + o)*HH0 + h)*WW0 + w0 + w4] = outv;
        }
    }
}

// ---------------- K3: GDN via mma.sync, chunked gamma -> 2 CTAs/SM ----------------
#define GZ_HI  0
#define GZ_LO  34816
#define GB_OFS 69632          // 2 x 12288 gamma chunk buffers
#define SMEM_GDN 94208
#define S_OFS  0              // s[o:128][132] f32 overlays z after mma

__global__ void __launch_bounds__(256, 2) k_gdn_mma(const float* __restrict__ beta) {
    uint32_t sb = smem_u32(smc);
    int t = threadIdx.x, l = t & 31, wid = t >> 5;
    int warp_m = wid & 1;          // o half (64 each)
    int warp_n = wid >> 1;         // px quarter (32 each)

    size_t p0 = (size_t)blockIdx.x * 128;
    int b   = (int)(p0 >> 16);
    int hw0 = (int)(p0 & 65535);
    float* yb = g_y + (size_t)b*CO*HWSZ + hw0;

    // prefetch gamma chunk 0
    for (int i = t; i < 768; i += 256)
        cpa16(sb + GB_OFS + i*16, g_gB2 + i*16);
    cpa_commit();

    // stage z = y^2 as [c rows][128 px] bf16 hi/lo, 272B stride (float4 reads)
    for (int i = t; i < 4096; i += 256) {
        int c = i >> 5, p4 = (i & 31) * 4;
        float4 v = *(const float4*)&yb[(size_t)c*HWSZ + p4];
        float z0 = v.x*v.x, z1 = v.y*v.y, z2 = v.z*v.z, z3 = v.w*v.w;
        __nv_bfloat162 hp0, hp1, lp0, lp1;
        hp0.x = __float2bfloat16(z0); hp0.y = __float2bfloat16(z1);
        hp1.x = __float2bfloat16(z2); hp1.y = __float2bfloat16(z3);
        lp0.x = __float2bfloat16(z0 - __bfloat162float(hp0.x));
        lp0.y = __float2bfloat16(z1 - __bfloat162float(hp0.y));
        lp1.x = __float2bfloat16(z2 - __bfloat162float(hp1.x));
        lp1.y = __float2bfloat16(z3 - __bfloat162float(hp1.y));
        int off = c*272 + p4*2;
        *(__nv_bfloat162*)(smc + GZ_HI + off)     = hp0;
        *(__nv_bfloat162*)(smc + GZ_HI + off + 4) = hp1;
        *(__nv_bfloat162*)(smc + GZ_LO + off)     = lp0;
        *(__nv_bfloat162*)(smc + GZ_LO + off + 4) = lp1;
    }
    cpa_wait0();
    __syncthreads();

    float sacc[4][4][4];
    #pragma unroll
    for (int mi = 0; mi < 4; ++mi)
        #pragma unroll
        for (int ni = 0; ni < 4; ++ni)
            #pragma unroll
            for (int k = 0; k < 4; ++k) sacc[mi][ni][k] = 0.f;

    int lane15 = l & 15;
    int kh8 = ((l >> 4) & 1) * 8;
    int noff = ((l >> 4) & 1) * 8;

    for (int ks = 0; ks < 8; ++ks) {
        if (ks < 7) {
            uint32_t dst = sb + GB_OFS + ((ks + 1) & 1)*12288;
            const unsigned char* src = g_gB2 + (ks + 1)*12288;
            for (int i = t; i < 768; i += 256)
                cpa16(dst + i*16, src + i*16);
        }
        cpa_commit();

        int k0 = ks * 16;
        uint32_t gbuf = sb + GB_OFS + (ks & 1)*12288;
        uint32_t aH[4][4], aL[4][4];
        #pragma unroll
        for (int mi = 0; mi < 4; ++mi) {
            uint32_t off = (uint32_t)((warp_m*64 + mi*16 + lane15)*48 + kh8*2);
            ldsm4(aH[mi], gbuf + off);
            ldsm4(aL[mi], gbuf + 6144 + off);
        }
        uint32_t bH[2][4], bL[2][4];
        #pragma unroll
        for (int n2 = 0; n2 < 2; ++n2) {
            uint32_t boff = (uint32_t)((k0 + lane15)*272 + (warp_n*32 + n2*16 + noff)*2);
            ldsm4t(bH[n2], sb + GZ_HI + boff);
            ldsm4t(bL[n2], sb + GZ_LO + boff);
        }
        #pragma unroll
        for (int mi = 0; mi < 4; ++mi)
            #pragma unroll
            for (int ni = 0; ni < 4; ++ni) {
                const uint32_t* bh = &bH[ni >> 1][(ni & 1)*2];
                const uint32_t* bl = &bL[ni >> 1][(ni & 1)*2];
                mma16816(sacc[mi][ni], aH[mi], bh);
                mma16816(sacc[mi][ni], aH[mi], bl);
                mma16816(sacc[mi][ni], aL[mi], bh);
            }

        cpa_wait0();
        __syncthreads();
    }

    // s frags -> S[o][132] (overlays z)
    float* S = (float*)(smc + S_OFS);
    #pragma unroll
    for (int mi = 0; mi < 4; ++mi)
        #pragma unroll
        for (int ni = 0; ni < 4; ++ni) {
            int o  = warp_m*64 + mi*16 + (l >> 2);
            int px = warp_n*32 + ni*8 + 2*(l & 3);
            S[o*132 + px]           = sacc[mi][ni][0];
            S[o*132 + px + 1]       = sacc[mi][ni][1];
            S[(o + 8)*132 + px]     = sacc[mi][ni][2];
            S[(o + 8)*132 + px + 1] = sacc[mi][ni][3];
        }
    __syncthreads();

    // final: y = y * rsqrt(beta + s) * mask, float4 everywhere
    int px4 = (t & 31) * 4;
    int ob = t >> 5;               // 0..7
    float4 mv4 = *(const float4*)&g_mvalid[p0 + px4];
    #pragma unroll
    for (int oo = 0; oo < 16; ++oo) {
        int o = ob + oo*8;
        float bo = beta[o];
        float4 s4 = *(const float4*)&S[o*132 + px4];
        size_t ad = (size_t)o*HWSZ + px4;
        float4 xv = *(const float4*)&yb[ad];
        float4 r;
        r.x = xv.x * rsqrtf(bo + s4.x) * mv4.x;
        r.y = xv.y * rsqrtf(bo + s4.y) * mv4.y;
        r.z = xv.z * rsqrtf(bo + s4.z) * mv4.z;
        r.w = xv.w * rsqrtf(bo + s4.w) * mv4.w;
        *(float4*)&yb[ad] = r;
    }
}

// ---------------- K4: fused DWT (rows + cols in one pass) -> 4 bands ----------------
#define DX_OFS 0          // xs[39][256] floats
#define DL_OFS 9984       // lo[16][260]
#define DH_OFS 14144      // hi[16][260]
#define SMEM_DWT 73216    // 18304 floats

__global__ void __launch_bounds__(256) k_dwt_fused(float* __restrict__ out) {
    float* sm = (float*)smc;
    float* xs = sm + DX_OFS;
    float* lo = sm + DL_OFS;
    float* hi = sm + DH_OFS;

    int t = threadIdx.x;
    int hr0 = blockIdx.x * 16;
    int bc  = blockIdx.y;
    const float* img = g_y + (size_t)bc*HWSZ;

    // float4 stage: 39 rows x 64 float4
    for (int i = t; i < 2496; i += 256) {
        int r = i >> 6, w4 = (i & 63) * 4;
        int h = refl(2*hr0 - 4 + r, HH0);
        *(float4*)&xs[r*256 + w4] = *(const float4*)&img[h*WW0 + w4];
    }
    __syncthreads();

    {
        int w = t;
        #pragma unroll 4
        for (int d = 0; d < 16; ++d) {
            const float* col = xs + 2*d*256 + w;
            float a0 = col[0],      a1 = col[256],  a2 = col[512],  a3 = col[768];
            float a4 = col[1024],   a5 = col[1280], a6 = col[1536], a7 = col[1792];
            float a8 = col[2048];
            float lv = c_H0[0]*a0 + c_H0[1]*a1 + c_H0[2]*a2 + c_H0[3]*a3 + c_H0[4]*a4
                     + c_H0[5]*a5 + c_H0[6]*a6 + c_H0[7]*a7 + c_H0[8]*a8;
            float hv = c_H1[0]*a1 + c_H1[1]*a2 + c_H1[2]*a3 + c_H1[3]*a4
                     + c_H1[4]*a5 + c_H1[5]*a6 + c_H1[6]*a7;
            lo[d*260 + w] = lv;
            hi[d*260 + w] = hv;
        }
    }
    __syncthreads();

    size_t obase = (size_t)bc*HD*WD;
    for (int i = t; i < 2048; i += 256) {
        int wr = i & 127, d = i >> 7;
        const float* lrow = lo + d*260;
        const float* hrow = hi + d*260;
        float rl[9], rh[9];
        #pragma unroll
        for (int k = 0; k < 9; ++k) {
            int j = refl(2*wr + k - 4, WW0);
            rl[k] = lrow[j];
            rh[k] = hrow[j];
        }
        float ll = 0.f, lh = 0.f, hl = 0.f, hh = 0.f;
        #pragma unroll
        for (int k = 0; k < 9; ++k) { ll += c_H0[k]*rl[k]; hl += c_H0[k]*rh[k]; }
        #pragma unroll
        for (int k = 0; k < 7; ++k) { lh += c_H1[k]*rl[k+1]; hh += c_H1[k]*rh[k+1]; }
        size_t oidx = obase + (size_t)(hr0 + d)*WD + wr;
        out[OFS_LL + oidx] = ll;
        out[OFS_LH + oidx] = lh;
        out[OFS_HL + oidx] = hl;
        out[OFS_HH + oidx] = hh;
    }
}

// ---------------- K5: fused mask downsample (H + W in one pass) -> 4 mask bands ------
#define MK_X   0
#define MK_LO  9984
#define MK_HI  14080
#define SMEM_MASK 72704

__global__ void __launch_bounds__(256) k_mask_fused(float* __restrict__ out) {
    float* sm  = (float*)smc;
    float* ms  = sm + MK_X;     // [39][256]
    float* mlo = sm + MK_LO;    // [16][256]
    float* mhi = sm + MK_HI;    // [16][256]

    int t = threadIdx.x;
    int hr0 = blockIdx.x * 16;
    int b   = blockIdx.y;
    const float* mv = g_mvalid + (size_t)b*HWSZ;

    for (int i = t; i < 2496; i += 256) {
        int r = i >> 6, w4 = (i & 63) * 4;
        int h = refl(2*hr0 - 4 + r, HH0);
        *(float4*)&ms[r*256 + w4] = *(const float4*)&mv[h*WW0 + w4];
    }
    __syncthreads();

    {
        int w = t;
        #pragma unroll 4
        for (int d = 0; d < 16; ++d) {
            const float* col = ms + 2*d*256 + w;
            float s9 = 0.f, s7 = 0.f;
            #pragma unroll
            for (int k = 0; k < 9; ++k) {
                float v = col[k*256];
                s9 += v;
                if (k >= 1 && k <= 7) s7 += v;
            }
            mlo[d*256 + w] = (s9 > 0.f) ? 1.f : 0.f;
            mhi[d*256 + w] = (s7 > 0.f) ? 1.f : 0.f;
        }
    }
    __syncthreads();

    size_t obase = (size_t)b*HD*WD;
    for (int i = t; i < 2048; i += 256) {
        int wr = i & 127, d = i >> 7;
        const float* lrow = mlo + d*256;
        const float* hrow = mhi + d*256;
        float s9l = 0.f, s7l = 0.f, s9h = 0.f, s7h = 0.f;
        #pragma unroll
        for (int k = 0; k < 9; ++k) {
            int j = refl(2*wr + k - 4, WW0);
            float vl = lrow[j], vh = hrow[j];
            s9l += vl; s9h += vh;
            if (k >= 1 && k <= 7) { s7l += vl; s7h += vh; }
        }
        size_t oidx = obase + (size_t)(hr0 + d)*WD + wr;
        out[OFS_MLL + oidx] = (s9l > 0.f) ? 1.f : 0.f;
        out[OFS_MLH + oidx] = (s7l > 0.f) ? 1.f : 0.f;
        out[OFS_MHL + oidx] = (s9h > 0.f) ? 1.f : 0.f;
        out[OFS_MHH + oidx] = (s7h > 0.f) ? 1.f : 0.f;
    }
}

// ---------------- launch ----------------
extern "C" void kernel_launch(void* const* d_in, const int* in_sizes, int n_in,
                              void* d_out, int out_size) {
    const float* tensor = (const float*)d_in[0];
    const float* mask   = (const float*)d_in[1];
    const float* weight = (const float*)d_in[2];
    const float* bias   = (const float*)d_in[3];
    const float* u      = (const float*)d_in[4];
    const float* beta   = (const float*)d_in[5];
    const float* gamma  = (const float*)d_in[6];
    float* out = (float*)d_out;

    cudaFuncSetAttribute(k_conv_mma, cudaFuncAttributeMaxDynamicSharedMemorySize, SMEM_MMA);
    cudaFuncSetAttribute(k_gdn_mma, cudaFuncAttributeMaxDynamicSharedMemorySize, SMEM_GDN);
    cudaFuncSetAttribute(k_dwt_fused, cudaFuncAttributeMaxDynamicSharedMemorySize, SMEM_DWT);
    cudaFuncSetAttribute(k_mask_fused, cudaFuncAttributeMaxDynamicSharedMemorySize, SMEM_MASK);

    k_sigma<<<1, 576>>>(weight, u);
    k_prepw<<<288, 256>>>();
    k_prepg<<<64, 256>>>(gamma);
    k_ratio<<<(NB*HWSZ)/256, 256>>>(mask);
    k_conv_mma<<<dim3(4, 128, NB), 256, SMEM_MMA>>>(tensor, mask, bias);
    k_gdn_mma<<<(NB*HWSZ)/128, 256, SMEM_GDN>>>(beta);
    k_dwt_fused<<<dim3(8, NB*CO), 256, SMEM_DWT>>>(out);
    k_mask_fused<<<dim3(8, NB), 256, SMEM_MASK>>>(out);
}